// round 11
// baseline (speedup 1.0000x reference)
#include <cuda_runtime.h>
#include <cuda_fp16.h>
#include <cstdint>
#include <cstddef>

typedef unsigned long long u64;
typedef unsigned int u32;

#define B_TOT 2048
#define N_TOK 49
#define CDIM  256
#define NHEAD 8
#define HDIM  32
#define M_ROWS (B_TOT * N_TOK)      // 100352
#define NN 2401                      // 49*49

// -------- scratch (device globals: no allocation allowed) --------
__device__ __align__(16) __half g_qh[(size_t)B_TOT * NHEAD * N_TOK * HDIM];
__device__ __align__(16) __half g_kh[(size_t)B_TOT * NHEAD * N_TOK * HDIM];
__device__ __align__(16) __half g_vh[(size_t)B_TOT * NHEAD * N_TOK * HDIM];
__device__ __align__(16) __half g_xh[(size_t)M_ROWS * 256];    // x fp16
__device__ __align__(16) __half g_ah[(size_t)M_ROWS * 256];    // attn-out fp16
__device__ __align__(16) __half g_wqkv[768 * 256];             // fp16
__device__ __align__(16) __half g_wproj[256 * 256];            // fp16
__device__ float g_emb[64 * NHEAD * NN];   // exp(mask[w] + rel_pos_bias[h])

// -------- packed-fp32 helpers (fma.rn.f32x2) --------
__device__ __forceinline__ u64 pack2(float x, float y) {
    u64 r; asm("mov.b64 %0,{%1,%2};" : "=l"(r) : "f"(x), "f"(y)); return r;
}
__device__ __forceinline__ u64 pack2b(float x) {
    u64 r; asm("mov.b64 %0,{%1,%1};" : "=l"(r) : "f"(x)); return r;
}
__device__ __forceinline__ u64 ffma2(u64 a, u64 b, u64 c) {
    u64 d; asm("fma.rn.f32x2 %0,%1,%2,%3;" : "=l"(d) : "l"(a), "l"(b), "l"(c)); return d;
}
__device__ __forceinline__ float2 unpack2(u64 v) {
    float lo, hi; asm("mov.b64 {%0,%1},%2;" : "=f"(lo), "=f"(hi) : "l"(v));
    return make_float2(lo, hi);
}

// -------- smem / async-copy / mma helpers (standard PTX, sm_80-safe) --------
__device__ __forceinline__ u32 smem_u32(const void* p) {
    u32 a; asm("{ .reg .u64 t; cvta.to.shared.u64 t,%1; cvt.u32.u64 %0,t; }" : "=r"(a) : "l"(p));
    return a;
}
__device__ __forceinline__ void cp16(u32 dst, const void* src) {
    asm volatile("cp.async.cg.shared.global [%0], [%1], 16;" :: "r"(dst), "l"(src));
}
__device__ __forceinline__ void ldm4(u32* r, u32 addr) {
    asm volatile("ldmatrix.sync.aligned.m8n8.x4.shared.b16 {%0,%1,%2,%3},[%4];"
                 : "=r"(r[0]), "=r"(r[1]), "=r"(r[2]), "=r"(r[3]) : "r"(addr));
}
__device__ __forceinline__ void hmma16816(float* c, const u32* a, const u32* b) {
    asm volatile(
        "mma.sync.aligned.m16n8k16.row.col.f32.f16.f16.f32 "
        "{%0,%1,%2,%3},{%4,%5,%6,%7},{%8,%9},{%0,%1,%2,%3};"
        : "+f"(c[0]), "+f"(c[1]), "+f"(c[2]), "+f"(c[3])
        : "r"(a[0]), "r"(a[1]), "r"(a[2]), "r"(a[3]), "r"(b[0]), "r"(b[1]));
}

// -------- fp32 -> fp16: [R,256] f32 -> [R,256] half --------
__global__ void conv_h1(const float* __restrict__ src, __half* __restrict__ dst, int rows) {
    int t = blockIdx.x * blockDim.x + threadIdx.x;
    if (t >= rows * 64) return;
    int m = t >> 6, k4 = (t & 63) << 2;
    float4 v = *(const float4*)(src + (size_t)m * 256 + k4);
    __half2 a;
    __half* dh = dst + (size_t)m * 256 + k4;
    a.x = __float2half_rn(v.x); a.y = __float2half_rn(v.y); *(__half2*)(dh) = a;
    a.x = __float2half_rn(v.z); a.y = __float2half_rn(v.w); *(__half2*)(dh + 2) = a;
}

// -------- precompute exp(mask[w][i][j] + bias[h][i][j]) --------
__global__ void emb_kernel(const float* __restrict__ table,
                           const float* __restrict__ mask) {
    int t = blockIdx.x * blockDim.x + threadIdx.x;
    if (t >= 64 * NHEAD * NN) return;
    int w   = t / (NHEAD * NN);
    int rem = t - w * (NHEAD * NN);
    int h   = rem / NN;
    int ij  = rem - h * NN;
    int i = ij / 49, j = ij - i * 49;
    int ri = i / 7, ci = i - ri * 7;
    int rj = j / 7, cj = j - rj * 7;
    int idx = (ri - rj + 6) * 13 + (ci - cj + 6);
    g_emb[t] = __expf(mask[w * NN + ij] + table[idx * NHEAD + h]);
}

// -------- HMMA GEMM (1-term fp16): C = A[M,256] @ W[N,256]^T + bias --------
// MODE 0: q/k/v epilogue writes fp16. MODE 1: writes fp32 d_out.
#define TSTRIDE 112
#define TILE_B  (128 * TSTRIDE)
#define STAGE_B (2 * TILE_B)
#define GEMM_SMEM (2 * STAGE_B)

template<int MODE>
__global__ void __launch_bounds__(256) hgemm(const __half* __restrict__ Ah_,
                                             const __half* __restrict__ Wh_,
                                             const float* __restrict__ bias,
                                             float* __restrict__ out) {
    extern __shared__ char smem[];
    const u32 sb = smem_u32(smem);
    const int tid = threadIdx.x;
    const int wid = tid >> 5, lane = tid & 31;
    const int g = lane >> 2, t = lane & 3;
    const int wm = wid >> 2, wn = wid & 3;
    const int bn = blockIdx.x, bm = blockIdx.y;

    const char* Asrc = (const char*)(Ah_ + (size_t)(bm * 128) * 256);
    const char* Wsrc = (const char*)(Wh_ + (size_t)(bn * 128) * 256);

    float acc[4][4][4];
#pragma unroll
    for (int i = 0; i < 4; i++)
#pragma unroll
        for (int j = 0; j < 4; j++)
#pragma unroll
            for (int q = 0; q < 4; q++) acc[i][j][q] = 0.f;

    const int r_ld = tid >> 2, c4 = tid & 3;

    auto issue = [&](int s) {
        const u32 dbase = sb + (s & 1) * STAGE_B;
#pragma unroll
        for (int i = 0; i < 2; i++) {
            const int r = r_ld + i * 64;
            const u32 d = dbase + r * TSTRIDE + c4 * 16;
            const size_t go = (size_t)r * 512 + (size_t)s * 64 + c4 * 16;
            cp16(d + 0 * TILE_B, Asrc + go);
            cp16(d + 1 * TILE_B, Wsrc + go);
        }
        asm volatile("cp.async.commit_group;" ::: "memory");
    };

    const u32 a_lrow = (lane & 15);
    const u32 a_lcol = (lane >> 4) << 4;
    const u32 b_lrow = ((lane >> 4) << 3) + (lane & 7);
    const u32 b_lcol = ((lane >> 3) & 1) << 4;

    issue(0);
    for (int s = 0; s < 8; s++) {
        if (s < 7) {
            issue(s + 1);
            asm volatile("cp.async.wait_group 1;" ::: "memory");
        } else {
            asm volatile("cp.async.wait_group 0;" ::: "memory");
        }
        __syncthreads();

        const u32 stb = sb + (s & 1) * STAGE_B;
        const u32 A0 = stb, B0 = stb + TILE_B;
#pragma unroll
        for (int s2 = 0; s2 < 2; s2++) {
            const u32 kbase = s2 * 32;
            u32 ah[4][4], bh[4][2];
#pragma unroll
            for (int mt = 0; mt < 4; mt++) {
                const u32 ra = (wm * 64 + mt * 16 + a_lrow) * TSTRIDE + kbase + a_lcol;
                ldm4(ah[mt], A0 + ra);
            }
#pragma unroll
            for (int nt2 = 0; nt2 < 2; nt2++) {
                u32 btmp[4];
                const u32 rb = (wn * 32 + nt2 * 16 + b_lrow) * TSTRIDE + kbase + b_lcol;
                ldm4(btmp, B0 + rb);
                bh[nt2 * 2 + 0][0] = btmp[0]; bh[nt2 * 2 + 0][1] = btmp[1];
                bh[nt2 * 2 + 1][0] = btmp[2]; bh[nt2 * 2 + 1][1] = btmp[3];
            }
#pragma unroll
            for (int mt = 0; mt < 4; mt++)
#pragma unroll
                for (int nt = 0; nt < 4; nt++)
                    hmma16816(acc[mt][nt], ah[mt], bh[nt]);
        }
        __syncthreads();
    }

#pragma unroll
    for (int nt = 0; nt < 4; nt++) {
        const int col0 = bn * 128 + wn * 32 + nt * 8 + t * 2;
        const float b0 = bias[col0], b1 = bias[col0 + 1];
        if (MODE == 0) {
            const int part = col0 >> 8;
            const int h = (col0 >> 5) & 7;
            const int d0 = col0 & 31;
            const float scale = (part == 0) ? 0.17677669529663687f : 1.0f;
            __half* dstb = (part == 0) ? g_qh : ((part == 1) ? g_kh : g_vh);
#pragma unroll
            for (int mt = 0; mt < 4; mt++) {
                const float* c = acc[mt][nt];
#pragma unroll
                for (int rr = 0; rr < 2; rr++) {
                    const int m = bm * 128 + wm * 64 + mt * 16 + g + rr * 8;
                    const int bidx = m / 49, tok = m - bidx * 49;
                    __half* dst = dstb + ((size_t)(bidx * 8 + h) * 49 + tok) * 32 + d0;
                    __half2 v;
                    v.x = __float2half_rn((c[rr * 2 + 0] + b0) * scale);
                    v.y = __float2half_rn((c[rr * 2 + 1] + b1) * scale);
                    *(__half2*)dst = v;
                }
            }
        } else {
#pragma unroll
            for (int mt = 0; mt < 4; mt++) {
                const float* c = acc[mt][nt];
#pragma unroll
                for (int rr = 0; rr < 2; rr++) {
                    const int m = bm * 128 + wm * 64 + mt * 16 + g + rr * 8;
                    float2 v;
                    v.x = c[rr * 2 + 0] + b0;
                    v.y = c[rr * 2 + 1] + b1;
                    *(float2*)(out + (size_t)m * 256 + col0) = v;
                }
            }
        }
    }
}

// -------- fused window attention: one block per (batch, head) --------
// Round-9 proven structure; q/k/v now loaded fp16 -> fp32 smem.
#define QS 33    // sQ row stride (conflict fix)
#define ES 53    // sE row stride (conflict fix)

__global__ void __launch_bounds__(128) attn_kernel(const float* __restrict__ fg,
                                                   const float* __restrict__ bg) {
    __shared__ float sQ[52 * QS];
    __shared__ __align__(16) float sKt[32 * 52];
    __shared__ __align__(16) float sV[49 * 32];
    __shared__ float sE[52 * ES];

    const int bh = blockIdx.x;
    const int b = bh >> 3, h = bh & 7;
    const int tid = threadIdx.x;
    const int warp = tid >> 5, lane = tid & 31;

    // zero pads: sQ rows 49..51, sKt cols 49..51
    if (tid < 96) {
        int r = 49 + tid / 32, k = tid % 32;
        sQ[r * QS + k] = 0.f;
        int kk = tid / 3, j = 49 + tid % 3;
        sKt[kk * 52 + j] = 0.f;
    }

    const size_t base = (size_t)bh * (N_TOK * HDIM);
    for (int f = tid; f < 196; f += 128) {   // 196 x 16B chunks (8 halfs each)
        const int j = f >> 2, k8 = (f & 3) << 3;
        uint4 qr = ((const uint4*)(g_qh + base))[f];
        uint4 kr = ((const uint4*)(g_kh + base))[f];
        uint4 vr = ((const uint4*)(g_vh + base))[f];
        const __half2* qh = (const __half2*)&qr;
        const __half2* kh = (const __half2*)&kr;
        const __half2* vh = (const __half2*)&vr;
#pragma unroll
        for (int i = 0; i < 4; i++) {
            float2 qf = __half22float2(qh[i]);
            sQ[j * QS + k8 + 2 * i]     = qf.x;
            sQ[j * QS + k8 + 2 * i + 1] = qf.y;
            float2 vf = __half22float2(vh[i]);
            sV[j * 32 + k8 + 2 * i]     = vf.x;
            sV[j * 32 + k8 + 2 * i + 1] = vf.y;
            float2 kf = __half22float2(kh[i]);
            sKt[(k8 + 2 * i) * 52 + j]     = kf.x;
            sKt[(k8 + 2 * i + 1) * 52 + j] = kf.y;
        }
    }
    __syncthreads();

    // ---- S = Q K^T, E0 = exp(S)*emb; 4x4 register tiles ----
    const float* embh = g_emb + (size_t)((b & 63) * NHEAD + h) * NN;
    for (int job = tid; job < 169; job += 128) {
        int iP = job / 13, jq = job - iP * 13;
        int i0 = iP * 4, j0 = jq * 4;
        u64 acc[4][2];
#pragma unroll
        for (int r = 0; r < 4; r++) { acc[r][0] = 0; acc[r][1] = 0; }
        const float* kt = sKt + j0;
        const float* q0 = sQ + i0 * QS;
#pragma unroll 8
        for (int k = 0; k < 32; k++) {
            float4 kv = *(const float4*)(kt + k * 52);
            u64 k0p = pack2(kv.x, kv.y), k1p = pack2(kv.z, kv.w);
#pragma unroll
            for (int r = 0; r < 4; r++) {
                u64 qp = pack2b(q0[r * QS + k]);
                acc[r][0] = ffma2(qp, k0p, acc[r][0]);
                acc[r][1] = ffma2(qp, k1p, acc[r][1]);
            }
        }
#pragma unroll
        for (int r = 0; r < 4; r++) {
            int row = i0 + r;
            if (row < 49) {
                float* er = sE + row * ES;
                const float* m0 = embh + row * 49;
                float2 v0 = unpack2(acc[r][0]), v1 = unpack2(acc[r][1]);
                er[j0] = __expf(v0.x) * m0[j0];
                if (j0 + 1 < 49) er[j0 + 1] = __expf(v0.y) * m0[j0 + 1];
                if (j0 + 2 < 49) er[j0 + 2] = __expf(v1.x) * m0[j0 + 2];
                if (j0 + 3 < 49) er[j0 + 3] = __expf(v1.y) * m0[j0 + 3];
            }
        }
    }
    __syncthreads();

    // ---- one-pass triple softmax (warp per row), fg/bg from gmem ----
    for (int row = warp; row < 49; row += 4) {
        float* er = sE + row * ES;
        const float* fgr = fg + (size_t)b * NN + row * 49;
        const float* bgr = bg + (size_t)b * NN + row * 49;
        bool ok = lane < 17;
        float e0  = er[lane];
        float fga = __expf(fgr[lane]), bga = __expf(bgr[lane]);
        float e0b = 0.f, fgb = 0.f, bgb = 0.f;
        if (ok) {
            e0b = er[lane + 32];
            fgb = __expf(fgr[lane + 32]);
            bgb = __expf(bgr[lane + 32]);
        }
        float s0 = e0 + e0b;
        float sf = e0 * fga + e0b * fgb;
        float sb2 = e0 * bga + e0b * bgb;
#pragma unroll
        for (int o = 16; o; o >>= 1) {
            s0  += __shfl_xor_sync(0xffffffffu, s0, o);
            sf  += __shfl_xor_sync(0xffffffffu, sf, o);
            sb2 += __shfl_xor_sync(0xffffffffu, sb2, o);
        }
        float r0 = 1.f / s0, rf = 1.f / sf, rb = 1.f / sb2;
        er[lane] = e0 * (r0 + rf * fga - rb * bga);
        if (ok) er[lane + 32] = e0b * (r0 + rf * fgb - rb * bgb);
    }
    __syncthreads();

    // ---- O = P @ V; 4x4 tiles; write plain fp16 ----
    if (tid < 104) {
        int iP = tid >> 3, dq = tid & 7;
        int i0 = iP * 4, d0 = dq * 4;
        u64 acc[4][2];
#pragma unroll
        for (int r = 0; r < 4; r++) { acc[r][0] = 0; acc[r][1] = 0; }
        const float* vp = sV + d0;
        const float* p0 = sE + i0 * ES;
#pragma unroll 7
        for (int j = 0; j < 49; j++) {
            float4 vv = *(const float4*)(vp + j * 32);
            u64 v0 = pack2(vv.x, vv.y), v1 = pack2(vv.z, vv.w);
#pragma unroll
            for (int r = 0; r < 4; r++) {
                u64 pp = pack2b(p0[r * ES + j]);
                acc[r][0] = ffma2(pp, v0, acc[r][0]);
                acc[r][1] = ffma2(pp, v1, acc[r][1]);
            }
        }
#pragma unroll
        for (int r = 0; r < 4; r++) {
            int row = i0 + r;
            if (row < 49) {
                __half* o0 = g_ah + ((size_t)(b * 49 + row)) * 256 + h * 32 + d0;
                float2 x0 = unpack2(acc[r][0]), x1 = unpack2(acc[r][1]);
                __half2 hh;
                hh.x = __float2half_rn(x0.x); hh.y = __float2half_rn(x0.y);
                *(__half2*)(o0) = hh;
                hh.x = __float2half_rn(x1.x); hh.y = __float2half_rn(x1.y);
                *(__half2*)(o0 + 2) = hh;
            }
        }
    }
}

extern "C" void kernel_launch(void* const* d_in, const int* in_sizes, int n_in,
                              void* d_out, int out_size) {
    const float* x      = (const float*)d_in[0];
    const float* mask   = (const float*)d_in[1];
    const float* fg     = (const float*)d_in[2];
    const float* bg     = (const float*)d_in[3];
    const float* qkv_w  = (const float*)d_in[4];
    const float* qkv_b  = (const float*)d_in[5];
    const float* proj_w = (const float*)d_in[6];
    const float* proj_b = (const float*)d_in[7];
    const float* table  = (const float*)d_in[8];
    float* out = (float*)d_out;

    cudaFuncSetAttribute(hgemm<0>, cudaFuncAttributeMaxDynamicSharedMemorySize, GEMM_SMEM);
    cudaFuncSetAttribute(hgemm<1>, cudaFuncAttributeMaxDynamicSharedMemorySize, GEMM_SMEM);

    __half* xh;    cudaGetSymbolAddress((void**)&xh,    g_xh);
    __half* wqkv;  cudaGetSymbolAddress((void**)&wqkv,  g_wqkv);
    __half* wproj; cudaGetSymbolAddress((void**)&wproj, g_wproj);
    __half* ah;    cudaGetSymbolAddress((void**)&ah,    g_ah);

    // Launch order chosen so the ncu capture slot lands on hgemm<0>.
    conv_h1<<<(M_ROWS * 64 + 255) / 256, 256>>>(x, xh, M_ROWS);          // 0
    conv_h1<<<(768 * 64 + 255) / 256, 256>>>(qkv_w, wqkv, 768);          // 1
    emb_kernel<<<(64 * NHEAD * NN + 255) / 256, 256>>>(table, mask);     // 2
    hgemm<0><<<dim3(6, 784), 256, GEMM_SMEM>>>(xh, wqkv, qkv_b, nullptr);// 3
    attn_kernel<<<B_TOT * NHEAD, 128>>>(fg, bg);                         // 4
    conv_h1<<<(256 * 64 + 255) / 256, 256>>>(proj_w, wproj, 256);        // 5
    hgemm<1><<<dim3(2, 784), 256, GEMM_SMEM>>>(ah, wproj, proj_b, out);  // 6
}

// round 12
// speedup vs baseline: 1.0339x; 1.0339x over previous
#include <cuda_runtime.h>
#include <cuda_fp16.h>
#include <cstdint>
#include <cstddef>

typedef unsigned long long u64;
typedef unsigned int u32;

#define B_TOT 2048
#define N_TOK 49
#define CDIM  256
#define NHEAD 8
#define HDIM  32
#define M_ROWS (B_TOT * N_TOK)      // 100352
#define NN 2401                      // 49*49

// -------- scratch (device globals: no allocation allowed) --------
__device__ __align__(16) float g_q[(size_t)B_TOT * NHEAD * N_TOK * HDIM];
__device__ __align__(16) float g_k[(size_t)B_TOT * NHEAD * N_TOK * HDIM];
__device__ __align__(16) float g_v[(size_t)B_TOT * NHEAD * N_TOK * HDIM];
__device__ __align__(16) __half g_xh[(size_t)M_ROWS * 256];    // x fp16
__device__ __align__(16) __half g_ah[(size_t)M_ROWS * 256];    // attn-out fp16
__device__ __align__(16) __half g_wqkv[768 * 256];             // fp16
__device__ __align__(16) __half g_wproj[256 * 256];            // fp16
__device__ float g_emb[64 * NHEAD * NN];   // exp(mask[w] + rel_pos_bias[h])

// -------- packed-fp32 helpers (fma.rn.f32x2) --------
__device__ __forceinline__ u64 pack2(float x, float y) {
    u64 r; asm("mov.b64 %0,{%1,%2};" : "=l"(r) : "f"(x), "f"(y)); return r;
}
__device__ __forceinline__ u64 pack2b(float x) {
    u64 r; asm("mov.b64 %0,{%1,%1};" : "=l"(r) : "f"(x)); return r;
}
__device__ __forceinline__ u64 ffma2(u64 a, u64 b, u64 c) {
    u64 d; asm("fma.rn.f32x2 %0,%1,%2,%3;" : "=l"(d) : "l"(a), "l"(b), "l"(c)); return d;
}
__device__ __forceinline__ float2 unpack2(u64 v) {
    float lo, hi; asm("mov.b64 {%0,%1},%2;" : "=f"(lo), "=f"(hi) : "l"(v));
    return make_float2(lo, hi);
}

// -------- smem / async-copy / mma helpers (standard PTX, sm_80-safe) --------
__device__ __forceinline__ u32 smem_u32(const void* p) {
    u32 a; asm("{ .reg .u64 t; cvta.to.shared.u64 t,%1; cvt.u32.u64 %0,t; }" : "=r"(a) : "l"(p));
    return a;
}
__device__ __forceinline__ void cp16(u32 dst, const void* src) {
    asm volatile("cp.async.cg.shared.global [%0], [%1], 16;" :: "r"(dst), "l"(src));
}
__device__ __forceinline__ void ldm4(u32* r, u32 addr) {
    asm volatile("ldmatrix.sync.aligned.m8n8.x4.shared.b16 {%0,%1,%2,%3},[%4];"
                 : "=r"(r[0]), "=r"(r[1]), "=r"(r[2]), "=r"(r[3]) : "r"(addr));
}
__device__ __forceinline__ void hmma16816(float* c, const u32* a, const u32* b) {
    asm volatile(
        "mma.sync.aligned.m16n8k16.row.col.f32.f16.f16.f32 "
        "{%0,%1,%2,%3},{%4,%5,%6,%7},{%8,%9},{%0,%1,%2,%3};"
        : "+f"(c[0]), "+f"(c[1]), "+f"(c[2]), "+f"(c[3])
        : "r"(a[0]), "r"(a[1]), "r"(a[2]), "r"(a[3]), "r"(b[0]), "r"(b[1]));
}

// -------- fp32 -> fp16: [R,256] f32 -> [R,256] half --------
__global__ void conv_h1(const float* __restrict__ src, __half* __restrict__ dst, int rows) {
    int t = blockIdx.x * blockDim.x + threadIdx.x;
    if (t >= rows * 64) return;
    int m = t >> 6, k4 = (t & 63) << 2;
    float4 v = *(const float4*)(src + (size_t)m * 256 + k4);
    __half2 a;
    __half* dh = dst + (size_t)m * 256 + k4;
    a.x = __float2half_rn(v.x); a.y = __float2half_rn(v.y); *(__half2*)(dh) = a;
    a.x = __float2half_rn(v.z); a.y = __float2half_rn(v.w); *(__half2*)(dh + 2) = a;
}

// -------- precompute exp(mask[w][i][j] + bias[h][i][j]) --------
__global__ void emb_kernel(const float* __restrict__ table,
                           const float* __restrict__ mask) {
    int t = blockIdx.x * blockDim.x + threadIdx.x;
    if (t >= 64 * NHEAD * NN) return;
    int w   = t / (NHEAD * NN);
    int rem = t - w * (NHEAD * NN);
    int h   = rem / NN;
    int ij  = rem - h * NN;
    int i = ij / 49, j = ij - i * 49;
    int ri = i / 7, ci = i - ri * 7;
    int rj = j / 7, cj = j - rj * 7;
    int idx = (ri - rj + 6) * 13 + (ci - cj + 6);
    g_emb[t] = __expf(mask[w * NN + ij] + table[idx * NHEAD + h]);
}

// -------- HMMA GEMM (1-term fp16): C = A[M,256] @ W[N,256]^T + bias --------
// CTA 128x128, 8 warps, warp 64x32, BK=32 sliced x8, double-buffered.
// __launch_bounds__(256,2): cap regs at 128 -> 2 CTAs/SM (occupancy fix).
#define TSTRIDE 112
#define TILE_B  (128 * TSTRIDE)
#define STAGE_B (2 * TILE_B)
#define GEMM_SMEM (2 * STAGE_B)

template<int MODE>
__global__ void __launch_bounds__(256, 2) hgemm(const __half* __restrict__ Ah_,
                                                const __half* __restrict__ Wh_,
                                                const float* __restrict__ bias,
                                                float* __restrict__ out) {
    extern __shared__ char smem[];
    const u32 sb = smem_u32(smem);
    const int tid = threadIdx.x;
    const int wid = tid >> 5, lane = tid & 31;
    const int g = lane >> 2, t = lane & 3;
    const int wm = wid >> 2, wn = wid & 3;
    const int bn = blockIdx.x, bm = blockIdx.y;

    const char* Asrc = (const char*)(Ah_ + (size_t)(bm * 128) * 256);
    const char* Wsrc = (const char*)(Wh_ + (size_t)(bn * 128) * 256);

    float acc[4][4][4];
#pragma unroll
    for (int i = 0; i < 4; i++)
#pragma unroll
        for (int j = 0; j < 4; j++)
#pragma unroll
            for (int q = 0; q < 4; q++) acc[i][j][q] = 0.f;

    const int r_ld = tid >> 2, c4 = tid & 3;

    auto issue = [&](int s) {
        const u32 dbase = sb + (s & 1) * STAGE_B;
#pragma unroll
        for (int i = 0; i < 2; i++) {
            const int r = r_ld + i * 64;
            const u32 d = dbase + r * TSTRIDE + c4 * 16;
            const size_t go = (size_t)r * 512 + (size_t)s * 64 + c4 * 16;
            cp16(d + 0 * TILE_B, Asrc + go);
            cp16(d + 1 * TILE_B, Wsrc + go);
        }
        asm volatile("cp.async.commit_group;" ::: "memory");
    };

    const u32 a_lrow = (lane & 15);
    const u32 a_lcol = (lane >> 4) << 4;
    const u32 b_lrow = ((lane >> 4) << 3) + (lane & 7);
    const u32 b_lcol = ((lane >> 3) & 1) << 4;

    issue(0);
    for (int s = 0; s < 8; s++) {
        if (s < 7) {
            issue(s + 1);
            asm volatile("cp.async.wait_group 1;" ::: "memory");
        } else {
            asm volatile("cp.async.wait_group 0;" ::: "memory");
        }
        __syncthreads();

        const u32 stb = sb + (s & 1) * STAGE_B;
        const u32 A0 = stb, B0 = stb + TILE_B;
#pragma unroll
        for (int s2 = 0; s2 < 2; s2++) {
            const u32 kbase = s2 * 32;
            u32 ah[4][4], bh[4][2];
#pragma unroll
            for (int mt = 0; mt < 4; mt++) {
                const u32 ra = (wm * 64 + mt * 16 + a_lrow) * TSTRIDE + kbase + a_lcol;
                ldm4(ah[mt], A0 + ra);
            }
#pragma unroll
            for (int nt2 = 0; nt2 < 2; nt2++) {
                u32 btmp[4];
                const u32 rb = (wn * 32 + nt2 * 16 + b_lrow) * TSTRIDE + kbase + b_lcol;
                ldm4(btmp, B0 + rb);
                bh[nt2 * 2 + 0][0] = btmp[0]; bh[nt2 * 2 + 0][1] = btmp[1];
                bh[nt2 * 2 + 1][0] = btmp[2]; bh[nt2 * 2 + 1][1] = btmp[3];
            }
#pragma unroll
            for (int mt = 0; mt < 4; mt++)
#pragma unroll
                for (int nt = 0; nt < 4; nt++)
                    hmma16816(acc[mt][nt], ah[mt], bh[nt]);
        }
        __syncthreads();
    }

#pragma unroll
    for (int nt = 0; nt < 4; nt++) {
        const int col0 = bn * 128 + wn * 32 + nt * 8 + t * 2;
        const float b0 = bias[col0], b1 = bias[col0 + 1];
        if (MODE == 0) {
            const int part = col0 >> 8;
            const int h = (col0 >> 5) & 7;
            const int d0 = col0 & 31;
            const float scale = (part == 0) ? 0.17677669529663687f : 1.0f;
            float* dstb = (part == 0) ? g_q : ((part == 1) ? g_k : g_v);
#pragma unroll
            for (int mt = 0; mt < 4; mt++) {
                const float* c = acc[mt][nt];
#pragma unroll
                for (int rr = 0; rr < 2; rr++) {
                    const int m = bm * 128 + wm * 64 + mt * 16 + g + rr * 8;
                    const int bidx = m / 49, tok = m - bidx * 49;
                    float* dst = dstb + ((size_t)(bidx * 8 + h) * 49 + tok) * 32 + d0;
                    float2 v;
                    v.x = (c[rr * 2 + 0] + b0) * scale;
                    v.y = (c[rr * 2 + 1] + b1) * scale;
                    *(float2*)dst = v;
                }
            }
        } else {
#pragma unroll
            for (int mt = 0; mt < 4; mt++) {
                const float* c = acc[mt][nt];
#pragma unroll
                for (int rr = 0; rr < 2; rr++) {
                    const int m = bm * 128 + wm * 64 + mt * 16 + g + rr * 8;
                    float2 v;
                    v.x = c[rr * 2 + 0] + b0;
                    v.y = c[rr * 2 + 1] + b1;
                    *(float2*)(out + (size_t)m * 256 + col0) = v;
                }
            }
        }
    }
}

// -------- fused window attention: one block per (batch, head) --------
// (round-9 proven version, fp32 q/k/v)
#define QS 33    // sQ row stride (conflict fix)
#define ES 53    // sE row stride (conflict fix)

__global__ void __launch_bounds__(128) attn_kernel(const float* __restrict__ fg,
                                                   const float* __restrict__ bg) {
    __shared__ float sQ[52 * QS];
    __shared__ __align__(16) float sKt[32 * 52];
    __shared__ __align__(16) float sV[49 * 32];
    __shared__ float sE[52 * ES];

    const int bh = blockIdx.x;
    const int b = bh >> 3, h = bh & 7;
    const int tid = threadIdx.x;
    const int warp = tid >> 5, lane = tid & 31;

    // zero pads: sQ rows 49..51, sKt cols 49..51
    if (tid < 96) {
        int r = 49 + tid / 32, k = tid % 32;
        sQ[r * QS + k] = 0.f;
        int kk = tid / 3, j = 49 + tid % 3;
        sKt[kk * 52 + j] = 0.f;
    }

    const size_t base = (size_t)bh * (N_TOK * HDIM);
    for (int f = tid; f < 392; f += 128) {
        int j = f >> 3, k4 = (f & 7) << 2;
        float4 qv = ((const float4*)(g_q + base))[f];
        sQ[j * QS + k4 + 0] = qv.x; sQ[j * QS + k4 + 1] = qv.y;
        sQ[j * QS + k4 + 2] = qv.z; sQ[j * QS + k4 + 3] = qv.w;
        ((float4*)sV)[f] = ((const float4*)(g_v + base))[f];
        float4 kv = ((const float4*)(g_k + base))[f];
        sKt[(k4 + 0) * 52 + j] = kv.x; sKt[(k4 + 1) * 52 + j] = kv.y;
        sKt[(k4 + 2) * 52 + j] = kv.z; sKt[(k4 + 3) * 52 + j] = kv.w;
    }
    __syncthreads();

    // ---- S = Q K^T, E0 = exp(S)*emb; 4x4 register tiles ----
    const float* embh = g_emb + (size_t)((b & 63) * NHEAD + h) * NN;
    for (int job = tid; job < 169; job += 128) {
        int iP = job / 13, jq = job - iP * 13;
        int i0 = iP * 4, j0 = jq * 4;
        u64 acc[4][2];
#pragma unroll
        for (int r = 0; r < 4; r++) { acc[r][0] = 0; acc[r][1] = 0; }
        const float* kt = sKt + j0;
        const float* q0 = sQ + i0 * QS;
#pragma unroll 8
        for (int k = 0; k < 32; k++) {
            float4 kv = *(const float4*)(kt + k * 52);
            u64 k0p = pack2(kv.x, kv.y), k1p = pack2(kv.z, kv.w);
#pragma unroll
            for (int r = 0; r < 4; r++) {
                u64 qp = pack2b(q0[r * QS + k]);
                acc[r][0] = ffma2(qp, k0p, acc[r][0]);
                acc[r][1] = ffma2(qp, k1p, acc[r][1]);
            }
        }
#pragma unroll
        for (int r = 0; r < 4; r++) {
            int row = i0 + r;
            if (row < 49) {
                float* er = sE + row * ES;
                const float* m0 = embh + row * 49;
                float2 v0 = unpack2(acc[r][0]), v1 = unpack2(acc[r][1]);
                er[j0] = __expf(v0.x) * m0[j0];
                if (j0 + 1 < 49) er[j0 + 1] = __expf(v0.y) * m0[j0 + 1];
                if (j0 + 2 < 49) er[j0 + 2] = __expf(v1.x) * m0[j0 + 2];
                if (j0 + 3 < 49) er[j0 + 3] = __expf(v1.y) * m0[j0 + 3];
            }
        }
    }
    __syncthreads();

    // ---- one-pass triple softmax (warp per row), fg/bg from gmem ----
    for (int row = warp; row < 49; row += 4) {
        float* er = sE + row * ES;
        const float* fgr = fg + (size_t)b * NN + row * 49;
        const float* bgr = bg + (size_t)b * NN + row * 49;
        bool ok = lane < 17;
        float e0  = er[lane];
        float fga = __expf(fgr[lane]), bga = __expf(bgr[lane]);
        float e0b = 0.f, fgb = 0.f, bgb = 0.f;
        if (ok) {
            e0b = er[lane + 32];
            fgb = __expf(fgr[lane + 32]);
            bgb = __expf(bgr[lane + 32]);
        }
        float s0 = e0 + e0b;
        float sf = e0 * fga + e0b * fgb;
        float sb2 = e0 * bga + e0b * bgb;
#pragma unroll
        for (int o = 16; o; o >>= 1) {
            s0  += __shfl_xor_sync(0xffffffffu, s0, o);
            sf  += __shfl_xor_sync(0xffffffffu, sf, o);
            sb2 += __shfl_xor_sync(0xffffffffu, sb2, o);
        }
        float r0 = 1.f / s0, rf = 1.f / sf, rb = 1.f / sb2;
        er[lane] = e0 * (r0 + rf * fga - rb * bga);
        if (ok) er[lane + 32] = e0b * (r0 + rf * fgb - rb * bgb);
    }
    __syncthreads();

    // ---- O = P @ V; 4x4 tiles; write plain fp16 ----
    if (tid < 104) {
        int iP = tid >> 3, dq = tid & 7;
        int i0 = iP * 4, d0 = dq * 4;
        u64 acc[4][2];
#pragma unroll
        for (int r = 0; r < 4; r++) { acc[r][0] = 0; acc[r][1] = 0; }
        const float* vp = sV + d0;
        const float* p0 = sE + i0 * ES;
#pragma unroll 7
        for (int j = 0; j < 49; j++) {
            float4 vv = *(const float4*)(vp + j * 32);
            u64 v0 = pack2(vv.x, vv.y), v1 = pack2(vv.z, vv.w);
#pragma unroll
            for (int r = 0; r < 4; r++) {
                u64 pp = pack2b(p0[r * ES + j]);
                acc[r][0] = ffma2(pp, v0, acc[r][0]);
                acc[r][1] = ffma2(pp, v1, acc[r][1]);
            }
        }
#pragma unroll
        for (int r = 0; r < 4; r++) {
            int row = i0 + r;
            if (row < 49) {
                __half* o0 = g_ah + ((size_t)(b * 49 + row)) * 256 + h * 32 + d0;
                float2 x0 = unpack2(acc[r][0]), x1 = unpack2(acc[r][1]);
                __half2 hh;
                hh.x = __float2half_rn(x0.x); hh.y = __float2half_rn(x0.y);
                *(__half2*)(o0) = hh;
                hh.x = __float2half_rn(x1.x); hh.y = __float2half_rn(x1.y);
                *(__half2*)(o0 + 2) = hh;
            }
        }
    }
}

extern "C" void kernel_launch(void* const* d_in, const int* in_sizes, int n_in,
                              void* d_out, int out_size) {
    const float* x      = (const float*)d_in[0];
    const float* mask   = (const float*)d_in[1];
    const float* fg     = (const float*)d_in[2];
    const float* bg     = (const float*)d_in[3];
    const float* qkv_w  = (const float*)d_in[4];
    const float* qkv_b  = (const float*)d_in[5];
    const float* proj_w = (const float*)d_in[6];
    const float* proj_b = (const float*)d_in[7];
    const float* table  = (const float*)d_in[8];
    float* out = (float*)d_out;

    cudaFuncSetAttribute(hgemm<0>, cudaFuncAttributeMaxDynamicSharedMemorySize, GEMM_SMEM);
    cudaFuncSetAttribute(hgemm<1>, cudaFuncAttributeMaxDynamicSharedMemorySize, GEMM_SMEM);

    __half* xh;    cudaGetSymbolAddress((void**)&xh,    g_xh);
    __half* wqkv;  cudaGetSymbolAddress((void**)&wqkv,  g_wqkv);
    __half* wproj; cudaGetSymbolAddress((void**)&wproj, g_wproj);
    __half* ah;    cudaGetSymbolAddress((void**)&ah,    g_ah);

    // Launch order keeps hgemm<0> in the ncu capture slot (#3).
    conv_h1<<<(M_ROWS * 64 + 255) / 256, 256>>>(x, xh, M_ROWS);          // 0
    conv_h1<<<(768 * 64 + 255) / 256, 256>>>(qkv_w, wqkv, 768);          // 1
    emb_kernel<<<(64 * NHEAD * NN + 255) / 256, 256>>>(table, mask);     // 2
    hgemm<0><<<dim3(6, 784), 256, GEMM_SMEM>>>(xh, wqkv, qkv_b, nullptr);// 3
    attn_kernel<<<B_TOT * NHEAD, 128>>>(fg, bg);                         // 4
    conv_h1<<<(256 * 64 + 255) / 256, 256>>>(proj_w, wproj, 256);        // 5
    hgemm<1><<<dim3(2, 784), 256, GEMM_SMEM>>>(ah, wproj, proj_b, out);  // 6
}

// round 13
// speedup vs baseline: 1.0664x; 1.0314x over previous
#include <cuda_runtime.h>
#include <cuda_fp16.h>
#include <cstdint>
#include <cstddef>

typedef unsigned long long u64;
typedef unsigned int u32;

#define B_TOT 2048
#define N_TOK 49
#define CDIM  256
#define NHEAD 8
#define HDIM  32
#define M_ROWS (B_TOT * N_TOK)      // 100352
#define NN 2401                      // 49*49
#define CONV_ROWS (M_ROWS + 768 + 256)

// -------- scratch (device globals: no allocation allowed) --------
__device__ __align__(16) float g_q[(size_t)B_TOT * NHEAD * N_TOK * HDIM];
__device__ __align__(16) float g_k[(size_t)B_TOT * NHEAD * N_TOK * HDIM];
__device__ __align__(16) float g_v[(size_t)B_TOT * NHEAD * N_TOK * HDIM];
__device__ __align__(16) __half g_xh[(size_t)M_ROWS * 256];    // x fp16
__device__ __align__(16) __half g_ah[(size_t)M_ROWS * 256];    // attn-out fp16
__device__ __align__(16) __half g_wqkv[768 * 256];             // fp16
__device__ __align__(16) __half g_wproj[256 * 256];            // fp16
__device__ float g_emb[64 * NHEAD * NN];   // exp(mask[w] + rel_pos_bias[h])

// -------- packed-fp32 helpers (fma.rn.f32x2) --------
__device__ __forceinline__ u64 pack2(float x, float y) {
    u64 r; asm("mov.b64 %0,{%1,%2};" : "=l"(r) : "f"(x), "f"(y)); return r;
}
__device__ __forceinline__ u64 pack2b(float x) {
    u64 r; asm("mov.b64 %0,{%1,%1};" : "=l"(r) : "f"(x)); return r;
}
__device__ __forceinline__ u64 ffma2(u64 a, u64 b, u64 c) {
    u64 d; asm("fma.rn.f32x2 %0,%1,%2,%3;" : "=l"(d) : "l"(a), "l"(b), "l"(c)); return d;
}
__device__ __forceinline__ float2 unpack2(u64 v) {
    float lo, hi; asm("mov.b64 {%0,%1},%2;" : "=f"(lo), "=f"(hi) : "l"(v));
    return make_float2(lo, hi);
}

// -------- smem / async-copy / mma helpers (standard PTX, sm_80-safe) --------
__device__ __forceinline__ u32 smem_u32(const void* p) {
    u32 a; asm("{ .reg .u64 t; cvta.to.shared.u64 t,%1; cvt.u32.u64 %0,t; }" : "=r"(a) : "l"(p));
    return a;
}
__device__ __forceinline__ void cp16(u32 dst, const void* src) {
    asm volatile("cp.async.cg.shared.global [%0], [%1], 16;" :: "r"(dst), "l"(src));
}
__device__ __forceinline__ void ldm4(u32* r, u32 addr) {
    asm volatile("ldmatrix.sync.aligned.m8n8.x4.shared.b16 {%0,%1,%2,%3},[%4];"
                 : "=r"(r[0]), "=r"(r[1]), "=r"(r[2]), "=r"(r[3]) : "r"(addr));
}
__device__ __forceinline__ void hmma16816(float* c, const u32* a, const u32* b) {
    asm volatile(
        "mma.sync.aligned.m16n8k16.row.col.f32.f16.f16.f32 "
        "{%0,%1,%2,%3},{%4,%5,%6,%7},{%8,%9},{%0,%1,%2,%3};"
        : "+f"(c[0]), "+f"(c[1]), "+f"(c[2]), "+f"(c[3])
        : "r"(a[0]), "r"(a[1]), "r"(a[2]), "r"(a[3]), "r"(b[0]), "r"(b[1]));
}

// -------- merged fp32 -> fp16 conversion: x | qkv_w | proj_w --------
__global__ void conv_all(const float* __restrict__ x,
                         const float* __restrict__ qkv_w,
                         const float* __restrict__ proj_w) {
    int t = blockIdx.x * blockDim.x + threadIdx.x;
    if (t >= CONV_ROWS * 64) return;
    int m = t >> 6, k4 = (t & 63) << 2;
    const float* src;
    __half* dst;
    int row;
    if (m < M_ROWS)            { src = x;      dst = g_xh;    row = m; }
    else if (m < M_ROWS + 768) { src = qkv_w;  dst = g_wqkv;  row = m - M_ROWS; }
    else                       { src = proj_w; dst = g_wproj; row = m - M_ROWS - 768; }
    float4 v = *(const float4*)(src + (size_t)row * 256 + k4);
    __half2 a;
    __half* dh = dst + (size_t)row * 256 + k4;
    a.x = __float2half_rn(v.x); a.y = __float2half_rn(v.y); *(__half2*)(dh) = a;
    a.x = __float2half_rn(v.z); a.y = __float2half_rn(v.w); *(__half2*)(dh + 2) = a;
}

// -------- precompute exp(mask[w][i][j] + bias[h][i][j]) --------
__global__ void emb_kernel(const float* __restrict__ table,
                           const float* __restrict__ mask) {
    int t = blockIdx.x * blockDim.x + threadIdx.x;
    if (t >= 64 * NHEAD * NN) return;
    int w   = t / (NHEAD * NN);
    int rem = t - w * (NHEAD * NN);
    int h   = rem / NN;
    int ij  = rem - h * NN;
    int i = ij / 49, j = ij - i * 49;
    int ri = i / 7, ci = i - ri * 7;
    int rj = j / 7, cj = j - rj * 7;
    int idx = (ri - rj + 6) * 13 + (ci - cj + 6);
    g_emb[t] = __expf(mask[w * NN + ij] + table[idx * NHEAD + h]);
}

// -------- HMMA GEMM (1-term fp16): C = A[M,256] @ W[N,256]^T + bias --------
// CTA 128x128, 8 warps, warp 64x32, BK=32 sliced x8, double-buffered.
// __launch_bounds__(256,2): 2 CTAs/SM (R12-verified: tensor 33->43%, 195->154us).
#define TSTRIDE 112
#define TILE_B  (128 * TSTRIDE)
#define STAGE_B (2 * TILE_B)
#define GEMM_SMEM (2 * STAGE_B)

template<int MODE>
__global__ void __launch_bounds__(256, 2) hgemm(const __half* __restrict__ Ah_,
                                                const __half* __restrict__ Wh_,
                                                const float* __restrict__ bias,
                                                float* __restrict__ out) {
    extern __shared__ char smem[];
    const u32 sb = smem_u32(smem);
    const int tid = threadIdx.x;
    const int wid = tid >> 5, lane = tid & 31;
    const int g = lane >> 2, t = lane & 3;
    const int wm = wid >> 2, wn = wid & 3;
    const int bn = blockIdx.x, bm = blockIdx.y;

    const char* Asrc = (const char*)(Ah_ + (size_t)(bm * 128) * 256);
    const char* Wsrc = (const char*)(Wh_ + (size_t)(bn * 128) * 256);

    float acc[4][4][4];
#pragma unroll
    for (int i = 0; i < 4; i++)
#pragma unroll
        for (int j = 0; j < 4; j++)
#pragma unroll
            for (int q = 0; q < 4; q++) acc[i][j][q] = 0.f;

    const int r_ld = tid >> 2, c4 = tid & 3;

    auto issue = [&](int s) {
        const u32 dbase = sb + (s & 1) * STAGE_B;
#pragma unroll
        for (int i = 0; i < 2; i++) {
            const int r = r_ld + i * 64;
            const u32 d = dbase + r * TSTRIDE + c4 * 16;
            const size_t go = (size_t)r * 512 + (size_t)s * 64 + c4 * 16;
            cp16(d + 0 * TILE_B, Asrc + go);
            cp16(d + 1 * TILE_B, Wsrc + go);
        }
        asm volatile("cp.async.commit_group;" ::: "memory");
    };

    const u32 a_lrow = (lane & 15);
    const u32 a_lcol = (lane >> 4) << 4;
    const u32 b_lrow = ((lane >> 4) << 3) + (lane & 7);
    const u32 b_lcol = ((lane >> 3) & 1) << 4;

    issue(0);
    for (int s = 0; s < 8; s++) {
        if (s < 7) {
            issue(s + 1);
            asm volatile("cp.async.wait_group 1;" ::: "memory");
        } else {
            asm volatile("cp.async.wait_group 0;" ::: "memory");
        }
        __syncthreads();

        const u32 stb = sb + (s & 1) * STAGE_B;
        const u32 A0 = stb, B0 = stb + TILE_B;
#pragma unroll
        for (int s2 = 0; s2 < 2; s2++) {
            const u32 kbase = s2 * 32;
            u32 ah[4][4], bh[4][2];
#pragma unroll
            for (int mt = 0; mt < 4; mt++) {
                const u32 ra = (wm * 64 + mt * 16 + a_lrow) * TSTRIDE + kbase + a_lcol;
                ldm4(ah[mt], A0 + ra);
            }
#pragma unroll
            for (int nt2 = 0; nt2 < 2; nt2++) {
                u32 btmp[4];
                const u32 rb = (wn * 32 + nt2 * 16 + b_lrow) * TSTRIDE + kbase + b_lcol;
                ldm4(btmp, B0 + rb);
                bh[nt2 * 2 + 0][0] = btmp[0]; bh[nt2 * 2 + 0][1] = btmp[1];
                bh[nt2 * 2 + 1][0] = btmp[2]; bh[nt2 * 2 + 1][1] = btmp[3];
            }
#pragma unroll
            for (int mt = 0; mt < 4; mt++)
#pragma unroll
                for (int nt = 0; nt < 4; nt++)
                    hmma16816(acc[mt][nt], ah[mt], bh[nt]);
        }
        __syncthreads();
    }

#pragma unroll
    for (int nt = 0; nt < 4; nt++) {
        const int col0 = bn * 128 + wn * 32 + nt * 8 + t * 2;
        const float b0 = bias[col0], b1 = bias[col0 + 1];
        if (MODE == 0) {
            const int part = col0 >> 8;
            const int h = (col0 >> 5) & 7;
            const int d0 = col0 & 31;
            const float scale = (part == 0) ? 0.17677669529663687f : 1.0f;
            float* dstb = (part == 0) ? g_q : ((part == 1) ? g_k : g_v);
#pragma unroll
            for (int mt = 0; mt < 4; mt++) {
                const float* c = acc[mt][nt];
#pragma unroll
                for (int rr = 0; rr < 2; rr++) {
                    const int m = bm * 128 + wm * 64 + mt * 16 + g + rr * 8;
                    const int bidx = m / 49, tok = m - bidx * 49;
                    float* dst = dstb + ((size_t)(bidx * 8 + h) * 49 + tok) * 32 + d0;
                    float2 v;
                    v.x = (c[rr * 2 + 0] + b0) * scale;
                    v.y = (c[rr * 2 + 1] + b1) * scale;
                    *(float2*)dst = v;
                }
            }
        } else {
#pragma unroll
            for (int mt = 0; mt < 4; mt++) {
                const float* c = acc[mt][nt];
#pragma unroll
                for (int rr = 0; rr < 2; rr++) {
                    const int m = bm * 128 + wm * 64 + mt * 16 + g + rr * 8;
                    float2 v;
                    v.x = c[rr * 2 + 0] + b0;
                    v.y = c[rr * 2 + 1] + b1;
                    *(float2*)(out + (size_t)m * 256 + col0) = v;
                }
            }
        }
    }
}

// -------- fused window attention: one block per (batch, head) --------
// (round-9 proven version, fp32 q/k/v)
#define QS 33    // sQ row stride (conflict fix)
#define ES 53    // sE row stride (conflict fix)

__global__ void __launch_bounds__(128) attn_kernel(const float* __restrict__ fg,
                                                   const float* __restrict__ bg) {
    __shared__ float sQ[52 * QS];
    __shared__ __align__(16) float sKt[32 * 52];
    __shared__ __align__(16) float sV[49 * 32];
    __shared__ float sE[52 * ES];

    const int bh = blockIdx.x;
    const int b = bh >> 3, h = bh & 7;
    const int tid = threadIdx.x;
    const int warp = tid >> 5, lane = tid & 31;

    // zero pads: sQ rows 49..51, sKt cols 49..51
    if (tid < 96) {
        int r = 49 + tid / 32, k = tid % 32;
        sQ[r * QS + k] = 0.f;
        int kk = tid / 3, j = 49 + tid % 3;
        sKt[kk * 52 + j] = 0.f;
    }

    const size_t base = (size_t)bh * (N_TOK * HDIM);
    for (int f = tid; f < 392; f += 128) {
        int j = f >> 3, k4 = (f & 7) << 2;
        float4 qv = ((const float4*)(g_q + base))[f];
        sQ[j * QS + k4 + 0] = qv.x; sQ[j * QS + k4 + 1] = qv.y;
        sQ[j * QS + k4 + 2] = qv.z; sQ[j * QS + k4 + 3] = qv.w;
        ((float4*)sV)[f] = ((const float4*)(g_v + base))[f];
        float4 kv = ((const float4*)(g_k + base))[f];
        sKt[(k4 + 0) * 52 + j] = kv.x; sKt[(k4 + 1) * 52 + j] = kv.y;
        sKt[(k4 + 2) * 52 + j] = kv.z; sKt[(k4 + 3) * 52 + j] = kv.w;
    }
    __syncthreads();

    // ---- S = Q K^T, E0 = exp(S)*emb; 4x4 register tiles ----
    const float* embh = g_emb + (size_t)((b & 63) * NHEAD + h) * NN;
    for (int job = tid; job < 169; job += 128) {
        int iP = job / 13, jq = job - iP * 13;
        int i0 = iP * 4, j0 = jq * 4;
        u64 acc[4][2];
#pragma unroll
        for (int r = 0; r < 4; r++) { acc[r][0] = 0; acc[r][1] = 0; }
        const float* kt = sKt + j0;
        const float* q0 = sQ + i0 * QS;
#pragma unroll 8
        for (int k = 0; k < 32; k++) {
            float4 kv = *(const float4*)(kt + k * 52);
            u64 k0p = pack2(kv.x, kv.y), k1p = pack2(kv.z, kv.w);
#pragma unroll
            for (int r = 0; r < 4; r++) {
                u64 qp = pack2b(q0[r * QS + k]);
                acc[r][0] = ffma2(qp, k0p, acc[r][0]);
                acc[r][1] = ffma2(qp, k1p, acc[r][1]);
            }
        }
#pragma unroll
        for (int r = 0; r < 4; r++) {
            int row = i0 + r;
            if (row < 49) {
                float* er = sE + row * ES;
                const float* m0 = embh + row * 49;
                float2 v0 = unpack2(acc[r][0]), v1 = unpack2(acc[r][1]);
                er[j0] = __expf(v0.x) * m0[j0];
                if (j0 + 1 < 49) er[j0 + 1] = __expf(v0.y) * m0[j0 + 1];
                if (j0 + 2 < 49) er[j0 + 2] = __expf(v1.x) * m0[j0 + 2];
                if (j0 + 3 < 49) er[j0 + 3] = __expf(v1.y) * m0[j0 + 3];
            }
        }
    }
    __syncthreads();

    // ---- one-pass triple softmax (warp per row), fg/bg from gmem ----
    for (int row = warp; row < 49; row += 4) {
        float* er = sE + row * ES;
        const float* fgr = fg + (size_t)b * NN + row * 49;
        const float* bgr = bg + (size_t)b * NN + row * 49;
        bool ok = lane < 17;
        float e0  = er[lane];
        float fga = __expf(fgr[lane]), bga = __expf(bgr[lane]);
        float e0b = 0.f, fgb = 0.f, bgb = 0.f;
        if (ok) {
            e0b = er[lane + 32];
            fgb = __expf(fgr[lane + 32]);
            bgb = __expf(bgr[lane + 32]);
        }
        float s0 = e0 + e0b;
        float sf = e0 * fga + e0b * fgb;
        float sb2 = e0 * bga + e0b * bgb;
#pragma unroll
        for (int o = 16; o; o >>= 1) {
            s0  += __shfl_xor_sync(0xffffffffu, s0, o);
            sf  += __shfl_xor_sync(0xffffffffu, sf, o);
            sb2 += __shfl_xor_sync(0xffffffffu, sb2, o);
        }
        float r0 = 1.f / s0, rf = 1.f / sf, rb = 1.f / sb2;
        er[lane] = e0 * (r0 + rf * fga - rb * bga);
        if (ok) er[lane + 32] = e0b * (r0 + rf * fgb - rb * bgb);
    }
    __syncthreads();

    // ---- O = P @ V; 4x4 tiles; write plain fp16 ----
    if (tid < 104) {
        int iP = tid >> 3, dq = tid & 7;
        int i0 = iP * 4, d0 = dq * 4;
        u64 acc[4][2];
#pragma unroll
        for (int r = 0; r < 4; r++) { acc[r][0] = 0; acc[r][1] = 0; }
        const float* vp = sV + d0;
        const float* p0 = sE + i0 * ES;
#pragma unroll 7
        for (int j = 0; j < 49; j++) {
            float4 vv = *(const float4*)(vp + j * 32);
            u64 v0 = pack2(vv.x, vv.y), v1 = pack2(vv.z, vv.w);
#pragma unroll
            for (int r = 0; r < 4; r++) {
                u64 pp = pack2b(p0[r * ES + j]);
                acc[r][0] = ffma2(pp, v0, acc[r][0]);
                acc[r][1] = ffma2(pp, v1, acc[r][1]);
            }
        }
#pragma unroll
        for (int r = 0; r < 4; r++) {
            int row = i0 + r;
            if (row < 49) {
                __half* o0 = g_ah + ((size_t)(b * 49 + row)) * 256 + h * 32 + d0;
                float2 x0 = unpack2(acc[r][0]), x1 = unpack2(acc[r][1]);
                __half2 hh;
                hh.x = __float2half_rn(x0.x); hh.y = __float2half_rn(x0.y);
                *(__half2*)(o0) = hh;
                hh.x = __float2half_rn(x1.x); hh.y = __float2half_rn(x1.y);
                *(__half2*)(o0 + 2) = hh;
            }
        }
    }
}

extern "C" void kernel_launch(void* const* d_in, const int* in_sizes, int n_in,
                              void* d_out, int out_size) {
    const float* x      = (const float*)d_in[0];
    const float* mask   = (const float*)d_in[1];
    const float* fg     = (const float*)d_in[2];
    const float* bg     = (const float*)d_in[3];
    const float* qkv_w  = (const float*)d_in[4];
    const float* qkv_b  = (const float*)d_in[5];
    const float* proj_w = (const float*)d_in[6];
    const float* proj_b = (const float*)d_in[7];
    const float* table  = (const float*)d_in[8];
    float* out = (float*)d_out;

    cudaFuncSetAttribute(hgemm<0>, cudaFuncAttributeMaxDynamicSharedMemorySize, GEMM_SMEM);
    cudaFuncSetAttribute(hgemm<1>, cudaFuncAttributeMaxDynamicSharedMemorySize, GEMM_SMEM);

    __half* xh;    cudaGetSymbolAddress((void**)&xh,    g_xh);
    __half* wqkv;  cudaGetSymbolAddress((void**)&wqkv,  g_wqkv);
    __half* wproj; cudaGetSymbolAddress((void**)&wproj, g_wproj);
    __half* ah;    cudaGetSymbolAddress((void**)&ah,    g_ah);

    // Launch order puts attn_kernel in the ncu capture slot (#3).
    conv_all<<<(CONV_ROWS * 64 + 255) / 256, 256>>>(x, qkv_w, proj_w);   // 0
    hgemm<0><<<dim3(6, 784), 256, GEMM_SMEM>>>(xh, wqkv, qkv_b, nullptr);// 1
    emb_kernel<<<(64 * NHEAD * NN + 255) / 256, 256>>>(table, mask);     // 2
    attn_kernel<<<B_TOT * NHEAD, 128>>>(fg, bg);                         // 3
    hgemm<1><<<dim3(2, 784), 256, GEMM_SMEM>>>(ah, wproj, proj_b, out);  // 4
}

// round 14
// speedup vs baseline: 1.2467x; 1.1691x over previous
#include <cuda_runtime.h>
#include <cuda_fp16.h>
#include <cstdint>
#include <cstddef>

typedef unsigned long long u64;
typedef unsigned int u32;

#define B_TOT 2048
#define N_TOK 49
#define CDIM  256
#define NHEAD 8
#define HDIM  32
#define M_ROWS (B_TOT * N_TOK)      // 100352
#define NN 2401                      // 49*49
#define CONV_ROWS (M_ROWS + 768 + 256)

// -------- scratch (device globals: no allocation allowed) --------
__device__ __align__(16) __half g_qh[(size_t)B_TOT * NHEAD * N_TOK * HDIM];
__device__ __align__(16) __half g_kh[(size_t)B_TOT * NHEAD * N_TOK * HDIM];
__device__ __align__(16) __half g_vh[(size_t)B_TOT * NHEAD * N_TOK * HDIM];
__device__ __align__(16) __half g_xh[(size_t)M_ROWS * 256];    // x fp16
__device__ __align__(16) __half g_ah[(size_t)M_ROWS * 256];    // attn-out fp16
__device__ __align__(16) __half g_wqkv[768 * 256];             // fp16
__device__ __align__(16) __half g_wproj[256 * 256];            // fp16
__device__ float g_emb[64 * NHEAD * NN];   // exp(mask[w] + rel_pos_bias[h])

// -------- smem / async-copy / mma helpers (standard PTX, sm_80-safe) --------
__device__ __forceinline__ u32 smem_u32(const void* p) {
    u32 a; asm("{ .reg .u64 t; cvta.to.shared.u64 t,%1; cvt.u32.u64 %0,t; }" : "=r"(a) : "l"(p));
    return a;
}
__device__ __forceinline__ void cp16(u32 dst, const void* src) {
    asm volatile("cp.async.cg.shared.global [%0], [%1], 16;" :: "r"(dst), "l"(src));
}
__device__ __forceinline__ void ldm4(u32* r, u32 addr) {
    asm volatile("ldmatrix.sync.aligned.m8n8.x4.shared.b16 {%0,%1,%2,%3},[%4];"
                 : "=r"(r[0]), "=r"(r[1]), "=r"(r[2]), "=r"(r[3]) : "r"(addr));
}
__device__ __forceinline__ void hmma16816(float* c, const u32* a, const u32* b) {
    asm volatile(
        "mma.sync.aligned.m16n8k16.row.col.f32.f16.f16.f32 "
        "{%0,%1,%2,%3},{%4,%5,%6,%7},{%8,%9},{%0,%1,%2,%3};"
        : "+f"(c[0]), "+f"(c[1]), "+f"(c[2]), "+f"(c[3])
        : "r"(a[0]), "r"(a[1]), "r"(a[2]), "r"(a[3]), "r"(b[0]), "r"(b[1]));
}

// -------- merged fp32 -> fp16 conversion: x | qkv_w | proj_w --------
__global__ void conv_all(const float* __restrict__ x,
                         const float* __restrict__ qkv_w,
                         const float* __restrict__ proj_w) {
    int t = blockIdx.x * blockDim.x + threadIdx.x;
    if (t >= CONV_ROWS * 64) return;
    int m = t >> 6, k4 = (t & 63) << 2;
    const float* src;
    __half* dst;
    int row;
    if (m < M_ROWS)            { src = x;      dst = g_xh;    row = m; }
    else if (m < M_ROWS + 768) { src = qkv_w;  dst = g_wqkv;  row = m - M_ROWS; }
    else                       { src = proj_w; dst = g_wproj; row = m - M_ROWS - 768; }
    float4 v = *(const float4*)(src + (size_t)row * 256 + k4);
    __half2 a;
    __half* dh = dst + (size_t)row * 256 + k4;
    a.x = __float2half_rn(v.x); a.y = __float2half_rn(v.y); *(__half2*)(dh) = a;
    a.x = __float2half_rn(v.z); a.y = __float2half_rn(v.w); *(__half2*)(dh + 2) = a;
}

// -------- precompute exp(mask[w][i][j] + bias[h][i][j]) --------
__global__ void emb_kernel(const float* __restrict__ table,
                           const float* __restrict__ mask) {
    int t = blockIdx.x * blockDim.x + threadIdx.x;
    if (t >= 64 * NHEAD * NN) return;
    int w   = t / (NHEAD * NN);
    int rem = t - w * (NHEAD * NN);
    int h   = rem / NN;
    int ij  = rem - h * NN;
    int i = ij / 49, j = ij - i * 49;
    int ri = i / 7, ci = i - ri * 7;
    int rj = j / 7, cj = j - rj * 7;
    int idx = (ri - rj + 6) * 13 + (ci - cj + 6);
    g_emb[t] = __expf(mask[w * NN + ij] + table[idx * NHEAD + h]);
}

// -------- HMMA GEMM (1-term fp16): C = A[M,256] @ W[N,256]^T + bias --------
// __launch_bounds__(256,2): R12-verified occupancy fix.
// MODE 0: writes fp16 q/k/v. MODE 1: writes fp32 d_out.
#define TSTRIDE 112
#define TILE_B  (128 * TSTRIDE)
#define STAGE_B (2 * TILE_B)
#define GEMM_SMEM (2 * STAGE_B)

template<int MODE>
__global__ void __launch_bounds__(256, 2) hgemm(const __half* __restrict__ Ah_,
                                                const __half* __restrict__ Wh_,
                                                const float* __restrict__ bias,
                                                float* __restrict__ out) {
    extern __shared__ char smem[];
    const u32 sb = smem_u32(smem);
    const int tid = threadIdx.x;
    const int wid = tid >> 5, lane = tid & 31;
    const int g = lane >> 2, t = lane & 3;
    const int wm = wid >> 2, wn = wid & 3;
    const int bn = blockIdx.x, bm = blockIdx.y;

    const char* Asrc = (const char*)(Ah_ + (size_t)(bm * 128) * 256);
    const char* Wsrc = (const char*)(Wh_ + (size_t)(bn * 128) * 256);

    float acc[4][4][4];
#pragma unroll
    for (int i = 0; i < 4; i++)
#pragma unroll
        for (int j = 0; j < 4; j++)
#pragma unroll
            for (int q = 0; q < 4; q++) acc[i][j][q] = 0.f;

    const int r_ld = tid >> 2, c4 = tid & 3;

    auto issue = [&](int s) {
        const u32 dbase = sb + (s & 1) * STAGE_B;
#pragma unroll
        for (int i = 0; i < 2; i++) {
            const int r = r_ld + i * 64;
            const u32 d = dbase + r * TSTRIDE + c4 * 16;
            const size_t go = (size_t)r * 512 + (size_t)s * 64 + c4 * 16;
            cp16(d + 0 * TILE_B, Asrc + go);
            cp16(d + 1 * TILE_B, Wsrc + go);
        }
        asm volatile("cp.async.commit_group;" ::: "memory");
    };

    const u32 a_lrow = (lane & 15);
    const u32 a_lcol = (lane >> 4) << 4;
    const u32 b_lrow = ((lane >> 4) << 3) + (lane & 7);
    const u32 b_lcol = ((lane >> 3) & 1) << 4;

    issue(0);
    for (int s = 0; s < 8; s++) {
        if (s < 7) {
            issue(s + 1);
            asm volatile("cp.async.wait_group 1;" ::: "memory");
        } else {
            asm volatile("cp.async.wait_group 0;" ::: "memory");
        }
        __syncthreads();

        const u32 stb = sb + (s & 1) * STAGE_B;
        const u32 A0 = stb, B0 = stb + TILE_B;
#pragma unroll
        for (int s2 = 0; s2 < 2; s2++) {
            const u32 kbase = s2 * 32;
            u32 ah[4][4], bh[4][2];
#pragma unroll
            for (int mt = 0; mt < 4; mt++) {
                const u32 ra = (wm * 64 + mt * 16 + a_lrow) * TSTRIDE + kbase + a_lcol;
                ldm4(ah[mt], A0 + ra);
            }
#pragma unroll
            for (int nt2 = 0; nt2 < 2; nt2++) {
                u32 btmp[4];
                const u32 rb = (wn * 32 + nt2 * 16 + b_lrow) * TSTRIDE + kbase + b_lcol;
                ldm4(btmp, B0 + rb);
                bh[nt2 * 2 + 0][0] = btmp[0]; bh[nt2 * 2 + 0][1] = btmp[1];
                bh[nt2 * 2 + 1][0] = btmp[2]; bh[nt2 * 2 + 1][1] = btmp[3];
            }
#pragma unroll
            for (int mt = 0; mt < 4; mt++)
#pragma unroll
                for (int nt = 0; nt < 4; nt++)
                    hmma16816(acc[mt][nt], ah[mt], bh[nt]);
        }
        __syncthreads();
    }

#pragma unroll
    for (int nt = 0; nt < 4; nt++) {
        const int col0 = bn * 128 + wn * 32 + nt * 8 + t * 2;
        const float b0 = bias[col0], b1 = bias[col0 + 1];
        if (MODE == 0) {
            const int part = col0 >> 8;
            const int h = (col0 >> 5) & 7;
            const int d0 = col0 & 31;
            const float scale = (part == 0) ? 0.17677669529663687f : 1.0f;
            __half* dstb = (part == 0) ? g_qh : ((part == 1) ? g_kh : g_vh);
#pragma unroll
            for (int mt = 0; mt < 4; mt++) {
                const float* c = acc[mt][nt];
#pragma unroll
                for (int rr = 0; rr < 2; rr++) {
                    const int m = bm * 128 + wm * 64 + mt * 16 + g + rr * 8;
                    const int bidx = m / 49, tok = m - bidx * 49;
                    __half* dst = dstb + ((size_t)(bidx * 8 + h) * 49 + tok) * 32 + d0;
                    __half2 v;
                    v.x = __float2half_rn((c[rr * 2 + 0] + b0) * scale);
                    v.y = __float2half_rn((c[rr * 2 + 1] + b1) * scale);
                    *(__half2*)dst = v;
                }
            }
        } else {
#pragma unroll
            for (int mt = 0; mt < 4; mt++) {
                const float* c = acc[mt][nt];
#pragma unroll
                for (int rr = 0; rr < 2; rr++) {
                    const int m = bm * 128 + wm * 64 + mt * 16 + g + rr * 8;
                    float2 v;
                    v.x = c[rr * 2 + 0] + b0;
                    v.y = c[rr * 2 + 1] + b1;
                    *(float2*)(out + (size_t)m * 256 + col0) = v;
                }
            }
        }
    }
}

// -------- HMMA fused attention: one block per (batch, head), 4 warps --------
// S = QK^T via m16n8k16 (fp16 in, fp32 acc); E0=exp(S)*emb in fp32 smem;
// triple softmax; P -> fp16; O = P V via m16n8k16; write g_ah fp16.
#define QKS 80    // sQh/sKh row stride BYTES (40 halfs, odd x16 -> conflict-free)
#define PVS 144   // sPh/sVt row stride BYTES (72 halfs, odd x16 -> conflict-free)

__global__ void __launch_bounds__(128) attn_kernel(const float* __restrict__ fg,
                                                   const float* __restrict__ bg) {
    __shared__ __align__(16) __half sQh[64 * 40];
    __shared__ __align__(16) __half sKh[64 * 40];
    __shared__ __align__(16) __half sVt[32 * 72];   // [d][j], cols j>=49 zero
    __shared__ __align__(16) __half sPh[64 * 72];   // [i][j], zero-initialized
    __shared__ __align__(16) float sE[49 * 53];

    const int bh = blockIdx.x;
    const int b = bh >> 3, h = bh & 7;
    const int tid = threadIdx.x;
    const int warp = tid >> 5, lane = tid & 31;
    const int g = lane >> 2, t = lane & 3;

    const u32 sQa = smem_u32(sQh), sKa = smem_u32(sKh);
    const u32 sVa = smem_u32(sVt), sPa = smem_u32(sPh);

    // zero sPh (576 uint4) + sVt (288 uint4)
    {
        const uint4 z = make_uint4(0u, 0u, 0u, 0u);
        for (int i = tid; i < 864; i += 128) {
            if (i < 576) ((uint4*)sPh)[i] = z;
            else         ((uint4*)sVt)[i - 576] = z;
        }
    }

    // load q/k (row-major fp16) + v transposed
    const size_t base = (size_t)bh * (N_TOK * HDIM);
    for (int f = tid; f < 196; f += 128) {
        const int j = f >> 2, c = f & 3;     // row j, 16B chunk c (8 halfs)
        uint4 qv = ((const uint4*)(g_qh + base))[f];
        *(uint4*)((char*)sQh + j * QKS + c * 16) = qv;
        uint4 kv = ((const uint4*)(g_kh + base))[f];
        *(uint4*)((char*)sKh + j * QKS + c * 16) = kv;
        uint4 vv = ((const uint4*)(g_vh + base))[f];
        const __half* vh = (const __half*)&vv;
#pragma unroll
        for (int i = 0; i < 8; i++) sVt[(c * 8 + i) * 72 + j] = vh[i];
    }
    __syncthreads();

    // ldmatrix per-lane offsets (proven in hgemm)
    const u32 a_lrow = (lane & 15);
    const u32 a_lcol = (lane >> 4) << 4;
    const u32 b_lrow = ((lane >> 4) << 3) + (lane & 7);
    const u32 b_lcol = ((lane >> 3) & 1) << 4;

    // ---- S = Q K^T: warp handles rows warp*16..+15, all 64 cols ----
    {
        float sAcc[8][4];
#pragma unroll
        for (int i = 0; i < 8; i++)
#pragma unroll
            for (int q = 0; q < 4; q++) sAcc[i][q] = 0.f;

#pragma unroll
        for (int ks = 0; ks < 2; ks++) {
            u32 a[4];
            ldm4(a, sQa + (warp * 16 + a_lrow) * QKS + ks * 32 + a_lcol);
#pragma unroll
            for (int nt2 = 0; nt2 < 4; nt2++) {
                u32 btmp[4];
                ldm4(btmp, sKa + (nt2 * 16 + b_lrow) * QKS + ks * 32 + b_lcol);
                hmma16816(sAcc[nt2 * 2 + 0], a, btmp + 0);
                hmma16816(sAcc[nt2 * 2 + 1], a, btmp + 2);
            }
        }

        // epilogue: E0 = exp(S) * emb -> sE (fp32), guarded
        const float* embh = g_emb + (size_t)((b & 63) * NHEAD + h) * NN;
        const int r0 = warp * 16 + g;
        const int r1 = r0 + 8;
#pragma unroll
        for (int nt = 0; nt < 8; nt++) {
            const int col = nt * 8 + t * 2;
            if (col < 49) {
                const bool c1ok = (col + 1 < 49);
                if (r0 < 49) {
                    sE[r0 * 53 + col] = __expf(sAcc[nt][0]) * embh[r0 * 49 + col];
                    if (c1ok) sE[r0 * 53 + col + 1] = __expf(sAcc[nt][1]) * embh[r0 * 49 + col + 1];
                }
                if (r1 < 49) {
                    sE[r1 * 53 + col] = __expf(sAcc[nt][2]) * embh[r1 * 49 + col];
                    if (c1ok) sE[r1 * 53 + col + 1] = __expf(sAcc[nt][3]) * embh[r1 * 49 + col + 1];
                }
            }
        }
    }
    __syncthreads();

    // ---- one-pass triple softmax (warp per row); P -> fp16 sPh ----
    for (int row = warp; row < 49; row += 4) {
        const float* er = sE + row * 53;
        const float* fgr = fg + (size_t)b * NN + row * 49;
        const float* bgr = bg + (size_t)b * NN + row * 49;
        bool ok = lane < 17;
        float e0  = er[lane];
        float fga = __expf(fgr[lane]), bga = __expf(bgr[lane]);
        float e0b = 0.f, fgb = 0.f, bgb = 0.f;
        if (ok) {
            e0b = er[lane + 32];
            fgb = __expf(fgr[lane + 32]);
            bgb = __expf(bgr[lane + 32]);
        }
        float s0 = e0 + e0b;
        float sf = e0 * fga + e0b * fgb;
        float sb2 = e0 * bga + e0b * bgb;
#pragma unroll
        for (int o = 16; o; o >>= 1) {
            s0  += __shfl_xor_sync(0xffffffffu, s0, o);
            sf  += __shfl_xor_sync(0xffffffffu, sf, o);
            sb2 += __shfl_xor_sync(0xffffffffu, sb2, o);
        }
        float r0f = 1.f / s0, rff = 1.f / sf, rbf = 1.f / sb2;
        sPh[row * 72 + lane] = __float2half_rn(e0 * (r0f + rff * fga - rbf * bga));
        if (ok) sPh[row * 72 + lane + 32] = __float2half_rn(e0b * (r0f + rff * fgb - rbf * bgb));
    }
    __syncthreads();

    // ---- O = P @ V: m=16/warp, n=32, k=64 ----
    {
        float oAcc[4][4];
#pragma unroll
        for (int i = 0; i < 4; i++)
#pragma unroll
            for (int q = 0; q < 4; q++) oAcc[i][q] = 0.f;

#pragma unroll
        for (int ks = 0; ks < 4; ks++) {
            u32 a[4];
            ldm4(a, sPa + (warp * 16 + a_lrow) * PVS + ks * 32 + a_lcol);
#pragma unroll
            for (int nt2 = 0; nt2 < 2; nt2++) {
                u32 btmp[4];
                ldm4(btmp, sVa + (nt2 * 16 + b_lrow) * PVS + ks * 32 + b_lcol);
                hmma16816(oAcc[nt2 * 2 + 0], a, btmp + 0);
                hmma16816(oAcc[nt2 * 2 + 1], a, btmp + 2);
            }
        }

        const int r0 = warp * 16 + g;
        const int r1 = r0 + 8;
#pragma unroll
        for (int nt = 0; nt < 4; nt++) {
            const int d = nt * 8 + t * 2;
            if (r0 < 49) {
                __half2 hh;
                hh.x = __float2half_rn(oAcc[nt][0]);
                hh.y = __float2half_rn(oAcc[nt][1]);
                *(__half2*)(g_ah + ((size_t)(b * 49 + r0)) * 256 + h * 32 + d) = hh;
            }
            if (r1 < 49) {
                __half2 hh;
                hh.x = __float2half_rn(oAcc[nt][2]);
                hh.y = __float2half_rn(oAcc[nt][3]);
                *(__half2*)(g_ah + ((size_t)(b * 49 + r1)) * 256 + h * 32 + d) = hh;
            }
        }
    }
}

extern "C" void kernel_launch(void* const* d_in, const int* in_sizes, int n_in,
                              void* d_out, int out_size) {
    const float* x      = (const float*)d_in[0];
    const float* mask   = (const float*)d_in[1];
    const float* fg     = (const float*)d_in[2];
    const float* bg     = (const float*)d_in[3];
    const float* qkv_w  = (const float*)d_in[4];
    const float* qkv_b  = (const float*)d_in[5];
    const float* proj_w = (const float*)d_in[6];
    const float* proj_b = (const float*)d_in[7];
    const float* table  = (const float*)d_in[8];
    float* out = (float*)d_out;

    cudaFuncSetAttribute(hgemm<0>, cudaFuncAttributeMaxDynamicSharedMemorySize, GEMM_SMEM);
    cudaFuncSetAttribute(hgemm<1>, cudaFuncAttributeMaxDynamicSharedMemorySize, GEMM_SMEM);

    __half* xh;    cudaGetSymbolAddress((void**)&xh,    g_xh);
    __half* wqkv;  cudaGetSymbolAddress((void**)&wqkv,  g_wqkv);
    __half* wproj; cudaGetSymbolAddress((void**)&wproj, g_wproj);
    __half* ah;    cudaGetSymbolAddress((void**)&ah,    g_ah);

    // Launch order puts attn_kernel in the ncu capture slot (#3).
    conv_all<<<(CONV_ROWS * 64 + 255) / 256, 256>>>(x, qkv_w, proj_w);   // 0
    hgemm<0><<<dim3(6, 784), 256, GEMM_SMEM>>>(xh, wqkv, qkv_b, nullptr);// 1
    emb_kernel<<<(64 * NHEAD * NN + 255) / 256, 256>>>(table, mask);     // 2
    attn_kernel<<<B_TOT * NHEAD, 128>>>(fg, bg);                         // 3
    hgemm<1><<<dim3(2, 784), 256, GEMM_SMEM>>>(ah, wproj, proj_b, out);  // 4
}

// round 16
// speedup vs baseline: 1.3334x; 1.0696x over previous
#include <cuda_runtime.h>
#include <cuda_fp16.h>
#include <cstdint>
#include <cstddef>

typedef unsigned long long u64;
typedef unsigned int u32;

#define B_TOT 2048
#define N_TOK 49
#define CDIM  256
#define NHEAD 8
#define HDIM  32
#define M_ROWS (B_TOT * N_TOK)      // 100352
#define NN 2401                      // 49*49
#define CONV_ROWS (M_ROWS + 768 + 256)

// -------- scratch (device globals: no allocation allowed) --------
__device__ __align__(16) __half g_qh[(size_t)B_TOT * NHEAD * N_TOK * HDIM];
__device__ __align__(16) __half g_kh[(size_t)B_TOT * NHEAD * N_TOK * HDIM];
__device__ __align__(16) __half g_vh[(size_t)B_TOT * NHEAD * N_TOK * HDIM];
__device__ __align__(16) __half g_xh[(size_t)M_ROWS * 256];    // x fp16
__device__ __align__(16) __half g_ah[(size_t)M_ROWS * 256];    // attn-out fp16
__device__ __align__(16) __half g_wqkv[768 * 256];             // fp16
__device__ __align__(16) __half g_wproj[256 * 256];            // fp16
__device__ float g_emb[64 * NHEAD * NN];   // exp(mask[w] + rel_pos_bias[h])

// -------- smem / async-copy / mma helpers (standard PTX, sm_80-safe) --------
__device__ __forceinline__ u32 smem_u32(const void* p) {
    u32 a; asm("{ .reg .u64 t; cvta.to.shared.u64 t,%1; cvt.u32.u64 %0,t; }" : "=r"(a) : "l"(p));
    return a;
}
__device__ __forceinline__ void cp16(u32 dst, const void* src) {
    asm volatile("cp.async.cg.shared.global [%0], [%1], 16;" :: "r"(dst), "l"(src));
}
__device__ __forceinline__ void ldm4(u32* r, u32 addr) {
    asm volatile("ldmatrix.sync.aligned.m8n8.x4.shared.b16 {%0,%1,%2,%3},[%4];"
                 : "=r"(r[0]), "=r"(r[1]), "=r"(r[2]), "=r"(r[3]) : "r"(addr));
}
__device__ __forceinline__ void hmma16816(float* c, const u32* a, const u32* b) {
    asm volatile(
        "mma.sync.aligned.m16n8k16.row.col.f32.f16.f16.f32 "
        "{%0,%1,%2,%3},{%4,%5,%6,%7},{%8,%9},{%0,%1,%2,%3};"
        : "+f"(c[0]), "+f"(c[1]), "+f"(c[2]), "+f"(c[3])
        : "r"(a[0]), "r"(a[1]), "r"(a[2]), "r"(a[3]), "r"(b[0]), "r"(b[1]));
}

// -------- merged fp32 -> fp16 conversion: x | qkv_w | proj_w --------
__global__ void conv_all(const float* __restrict__ x,
                         const float* __restrict__ qkv_w,
                         const float* __restrict__ proj_w) {
    int t = blockIdx.x * blockDim.x + threadIdx.x;
    if (t >= CONV_ROWS * 64) return;
    int m = t >> 6, k4 = (t & 63) << 2;
    const float* src;
    __half* dst;
    int row;
    if (m < M_ROWS)            { src = x;      dst = g_xh;    row = m; }
    else if (m < M_ROWS + 768) { src = qkv_w;  dst = g_wqkv;  row = m - M_ROWS; }
    else                       { src = proj_w; dst = g_wproj; row = m - M_ROWS - 768; }
    float4 v = *(const float4*)(src + (size_t)row * 256 + k4);
    __half2 a;
    __half* dh = dst + (size_t)row * 256 + k4;
    a.x = __float2half_rn(v.x); a.y = __float2half_rn(v.y); *(__half2*)(dh) = a;
    a.x = __float2half_rn(v.z); a.y = __float2half_rn(v.w); *(__half2*)(dh + 2) = a;
}

// -------- precompute exp(mask[w][i][j] + bias[h][i][j]) --------
__global__ void emb_kernel(const float* __restrict__ table,
                           const float* __restrict__ mask) {
    int t = blockIdx.x * blockDim.x + threadIdx.x;
    if (t >= 64 * NHEAD * NN) return;
    int w   = t / (NHEAD * NN);
    int rem = t - w * (NHEAD * NN);
    int h   = rem / NN;
    int ij  = rem - h * NN;
    int i = ij / 49, j = ij - i * 49;
    int ri = i / 7, ci = i - ri * 7;
    int rj = j / 7, cj = j - rj * 7;
    int idx = (ri - rj + 6) * 13 + (ci - cj + 6);
    g_emb[t] = __expf(mask[w * NN + ij] + table[idx * NHEAD + h]);
}

// -------- HMMA GEMM (1-term fp16): C = A[M,256] @ W[N,256]^T + bias --------
// __launch_bounds__(256,2): R12-verified occupancy fix.
// MODE 0: writes fp16 q/k/v. MODE 1: writes fp32 d_out.
#define TSTRIDE 112
#define TILE_B  (128 * TSTRIDE)
#define STAGE_B (2 * TILE_B)
#define GEMM_SMEM (2 * STAGE_B)

template<int MODE>
__global__ void __launch_bounds__(256, 2) hgemm(const __half* __restrict__ Ah_,
                                                const __half* __restrict__ Wh_,
                                                const float* __restrict__ bias,
                                                float* __restrict__ out) {
    extern __shared__ char smem[];
    const u32 sb = smem_u32(smem);
    const int tid = threadIdx.x;
    const int wid = tid >> 5, lane = tid & 31;
    const int g = lane >> 2, t = lane & 3;
    const int wm = wid >> 2, wn = wid & 3;
    const int bn = blockIdx.x, bm = blockIdx.y;

    const char* Asrc = (const char*)(Ah_ + (size_t)(bm * 128) * 256);
    const char* Wsrc = (const char*)(Wh_ + (size_t)(bn * 128) * 256);

    float acc[4][4][4];
#pragma unroll
    for (int i = 0; i < 4; i++)
#pragma unroll
        for (int j = 0; j < 4; j++)
#pragma unroll
            for (int q = 0; q < 4; q++) acc[i][j][q] = 0.f;

    const int r_ld = tid >> 2, c4 = tid & 3;

    auto issue = [&](int s) {
        const u32 dbase = sb + (s & 1) * STAGE_B;
#pragma unroll
        for (int i = 0; i < 2; i++) {
            const int r = r_ld + i * 64;
            const u32 d = dbase + r * TSTRIDE + c4 * 16;
            const size_t go = (size_t)r * 512 + (size_t)s * 64 + c4 * 16;
            cp16(d + 0 * TILE_B, Asrc + go);
            cp16(d + 1 * TILE_B, Wsrc + go);
        }
        asm volatile("cp.async.commit_group;" ::: "memory");
    };

    const u32 a_lrow = (lane & 15);
    const u32 a_lcol = (lane >> 4) << 4;
    const u32 b_lrow = ((lane >> 4) << 3) + (lane & 7);
    const u32 b_lcol = ((lane >> 3) & 1) << 4;

    issue(0);
    for (int s = 0; s < 8; s++) {
        if (s < 7) {
            issue(s + 1);
            asm volatile("cp.async.wait_group 1;" ::: "memory");
        } else {
            asm volatile("cp.async.wait_group 0;" ::: "memory");
        }
        __syncthreads();

        const u32 stb = sb + (s & 1) * STAGE_B;
        const u32 A0 = stb, B0 = stb + TILE_B;
#pragma unroll
        for (int s2 = 0; s2 < 2; s2++) {
            const u32 kbase = s2 * 32;
            u32 ah[4][4], bh[4][2];
#pragma unroll
            for (int mt = 0; mt < 4; mt++) {
                const u32 ra = (wm * 64 + mt * 16 + a_lrow) * TSTRIDE + kbase + a_lcol;
                ldm4(ah[mt], A0 + ra);
            }
#pragma unroll
            for (int nt2 = 0; nt2 < 2; nt2++) {
                u32 btmp[4];
                const u32 rb = (wn * 32 + nt2 * 16 + b_lrow) * TSTRIDE + kbase + b_lcol;
                ldm4(btmp, B0 + rb);
                bh[nt2 * 2 + 0][0] = btmp[0]; bh[nt2 * 2 + 0][1] = btmp[1];
                bh[nt2 * 2 + 1][0] = btmp[2]; bh[nt2 * 2 + 1][1] = btmp[3];
            }
#pragma unroll
            for (int mt = 0; mt < 4; mt++)
#pragma unroll
                for (int nt = 0; nt < 4; nt++)
                    hmma16816(acc[mt][nt], ah[mt], bh[nt]);
        }
        __syncthreads();
    }

#pragma unroll
    for (int nt = 0; nt < 4; nt++) {
        const int col0 = bn * 128 + wn * 32 + nt * 8 + t * 2;
        const float b0 = bias[col0], b1 = bias[col0 + 1];
        if (MODE == 0) {
            const int part = col0 >> 8;
            const int h = (col0 >> 5) & 7;
            const int d0 = col0 & 31;
            const float scale = (part == 0) ? 0.17677669529663687f : 1.0f;
            __half* dstb = (part == 0) ? g_qh : ((part == 1) ? g_kh : g_vh);
#pragma unroll
            for (int mt = 0; mt < 4; mt++) {
                const float* c = acc[mt][nt];
#pragma unroll
                for (int rr = 0; rr < 2; rr++) {
                    const int m = bm * 128 + wm * 64 + mt * 16 + g + rr * 8;
                    const int bidx = m / 49, tok = m - bidx * 49;
                    __half* dst = dstb + ((size_t)(bidx * 8 + h) * 49 + tok) * 32 + d0;
                    __half2 v;
                    v.x = __float2half_rn((c[rr * 2 + 0] + b0) * scale);
                    v.y = __float2half_rn((c[rr * 2 + 1] + b1) * scale);
                    *(__half2*)dst = v;
                }
            }
        } else {
#pragma unroll
            for (int mt = 0; mt < 4; mt++) {
                const float* c = acc[mt][nt];
#pragma unroll
                for (int rr = 0; rr < 2; rr++) {
                    const int m = bm * 128 + wm * 64 + mt * 16 + g + rr * 8;
                    float2 v;
                    v.x = c[rr * 2 + 0] + b0;
                    v.y = c[rr * 2 + 1] + b1;
                    *(float2*)(out + (size_t)m * 256 + col0) = v;
                }
            }
        }
    }
}

// -------- HMMA fused attention: one block per (batch, head), 4 warps --------
// Smem aliased: sPh reuses sQh/sKh space after the S phase (24.7KB, 8 blk/SM).
// RACE FIX (R15 failure): __syncthreads() between zero-init and data load.
#define QKS 80    // sQh/sKh row stride BYTES
#define PVS 144   // sPh/sVt row stride BYTES
#define OFF_Q  0
#define OFF_K  5120
#define OFF_P  0          // aliased over Q + part of K
#define OFF_V  10240
#define OFF_E  14848
#define SM_BYTES (14848 + 10400)   // 25248

__global__ void __launch_bounds__(128, 8) attn_kernel(const float* __restrict__ fg,
                                                      const float* __restrict__ bg) {
    __shared__ __align__(16) char sm[SM_BYTES];
    __half* sQh = (__half*)(sm + OFF_Q);
    __half* sKh = (__half*)(sm + OFF_K);
    __half* sPh = (__half*)(sm + OFF_P);   // alias of Q/K region
    __half* sVt = (__half*)(sm + OFF_V);
    float*  sE  = (float*)(sm + OFF_E);

    const int bh = blockIdx.x;
    const int b = bh >> 3, h = bh & 7;
    const int tid = threadIdx.x;
    const int warp = tid >> 5, lane = tid & 31;
    const int g = lane >> 2, t = lane & 3;

    const u32 sQa = smem_u32(sQh), sKa = smem_u32(sKh);
    const u32 sVa = smem_u32(sVt), sPa = smem_u32(sPh);

    // zero sVt (288 uint4) — pads col>=49 must be 0 for guard-free PV HMMA
    {
        const uint4 z = make_uint4(0u, 0u, 0u, 0u);
        for (int i = tid; i < 288; i += 128) ((uint4*)sVt)[i] = z;
    }
    __syncthreads();   // RACE FIX: zeroing must complete before V data lands

    // load q/k (row-major fp16) + v transposed
    const size_t base = (size_t)bh * (N_TOK * HDIM);
    for (int f = tid; f < 196; f += 128) {
        const int j = f >> 2, c = f & 3;     // row j, 16B chunk c (8 halfs)
        uint4 qv = ((const uint4*)(g_qh + base))[f];
        *(uint4*)((char*)sQh + j * QKS + c * 16) = qv;
        uint4 kv = ((const uint4*)(g_kh + base))[f];
        *(uint4*)((char*)sKh + j * QKS + c * 16) = kv;
        uint4 vv = ((const uint4*)(g_vh + base))[f];
        const __half* vh = (const __half*)&vv;
#pragma unroll
        for (int i = 0; i < 8; i++) sVt[(c * 8 + i) * 72 + j] = vh[i];
    }
    // q/k rows 49..63 are garbage — S rows/cols >=49 are discarded by guards.
    __syncthreads();

    // ldmatrix per-lane offsets
    const u32 a_lrow = (lane & 15);
    const u32 a_lcol = (lane >> 4) << 4;
    const u32 b_lrow = ((lane >> 4) << 3) + (lane & 7);
    const u32 b_lcol = ((lane >> 3) & 1) << 4;

    // ---- S = Q K^T: warp handles rows warp*16..+15, all 64 cols ----
    {
        float sAcc[8][4];
#pragma unroll
        for (int i = 0; i < 8; i++)
#pragma unroll
            for (int q = 0; q < 4; q++) sAcc[i][q] = 0.f;

#pragma unroll
        for (int ks = 0; ks < 2; ks++) {
            u32 a[4];
            ldm4(a, sQa + (warp * 16 + a_lrow) * QKS + ks * 32 + a_lcol);
#pragma unroll
            for (int nt2 = 0; nt2 < 4; nt2++) {
                u32 btmp[4];
                ldm4(btmp, sKa + (nt2 * 16 + b_lrow) * QKS + ks * 32 + b_lcol);
                hmma16816(sAcc[nt2 * 2 + 0], a, btmp + 0);
                hmma16816(sAcc[nt2 * 2 + 1], a, btmp + 2);
            }
        }

        // epilogue: E0 = exp(S) * emb -> sE (fp32), guarded
        const float* embh = g_emb + (size_t)((b & 63) * NHEAD + h) * NN;
        const int r0 = warp * 16 + g;
        const int r1 = r0 + 8;
#pragma unroll
        for (int nt = 0; nt < 8; nt++) {
            const int col = nt * 8 + t * 2;
            if (col < 49) {
                const bool c1ok = (col + 1 < 49);
                if (r0 < 49) {
                    sE[r0 * 53 + col] = __expf(sAcc[nt][0]) * embh[r0 * 49 + col];
                    if (c1ok) sE[r0 * 53 + col + 1] = __expf(sAcc[nt][1]) * embh[r0 * 49 + col + 1];
                }
                if (r1 < 49) {
                    sE[r1 * 53 + col] = __expf(sAcc[nt][2]) * embh[r1 * 49 + col];
                    if (c1ok) sE[r1 * 53 + col + 1] = __expf(sAcc[nt][3]) * embh[r1 * 49 + col + 1];
                }
            }
        }
    }
    __syncthreads();        // S-phase reads of sQh/sKh complete

    // zero the aliased sPh (576 uint4) — pads must be 0 for PV HMMA
    {
        const uint4 z = make_uint4(0u, 0u, 0u, 0u);
        for (int i = tid; i < 576; i += 128) ((uint4*)sPh)[i] = z;
    }
    __syncthreads();

    // ---- one-pass triple softmax (warp per row); P -> fp16 sPh ----
    for (int row = warp; row < 49; row += 4) {
        const float* er = sE + row * 53;
        const float* fgr = fg + (size_t)b * NN + row * 49;
        const float* bgr = bg + (size_t)b * NN + row * 49;
        bool ok = lane < 17;
        float e0  = er[lane];
        float fga = __expf(fgr[lane]), bga = __expf(bgr[lane]);
        float e0b = 0.f, fgb = 0.f, bgb = 0.f;
        if (ok) {
            e0b = er[lane + 32];
            fgb = __expf(fgr[lane + 32]);
            bgb = __expf(bgr[lane + 32]);
        }
        float s0 = e0 + e0b;
        float sf = e0 * fga + e0b * fgb;
        float sb2 = e0 * bga + e0b * bgb;
#pragma unroll
        for (int o = 16; o; o >>= 1) {
            s0  += __shfl_xor_sync(0xffffffffu, s0, o);
            sf  += __shfl_xor_sync(0xffffffffu, sf, o);
            sb2 += __shfl_xor_sync(0xffffffffu, sb2, o);
        }
        float r0f = 1.f / s0, rff = 1.f / sf, rbf = 1.f / sb2;
        sPh[row * 72 + lane] = __float2half_rn(e0 * (r0f + rff * fga - rbf * bga));
        if (ok) sPh[row * 72 + lane + 32] = __float2half_rn(e0b * (r0f + rff * fgb - rbf * bgb));
    }
    __syncthreads();

    // ---- O = P @ V: m=16/warp, n=32, k=64 ----
    {
        float oAcc[4][4];
#pragma unroll
        for (int i = 0; i < 4; i++)
#pragma unroll
            for (int q = 0; q < 4; q++) oAcc[i][q] = 0.f;

#pragma unroll
        for (int ks = 0; ks < 4; ks++) {
            u32 a[4];
            ldm4(a, sPa + (warp * 16 + a_lrow) * PVS + ks * 32 + a_lcol);
#pragma unroll
            for (int nt2 = 0; nt2 < 2; nt2++) {
                u32 btmp[4];
                ldm4(btmp, sVa + (nt2 * 16 + b_lrow) * PVS + ks * 32 + b_lcol);
                hmma16816(oAcc[nt2 * 2 + 0], a, btmp + 0);
                hmma16816(oAcc[nt2 * 2 + 1], a, btmp + 2);
            }
        }

        const int r0 = warp * 16 + g;
        const int r1 = r0 + 8;
#pragma unroll
        for (int nt = 0; nt < 4; nt++) {
            const int d = nt * 8 + t * 2;
            if (r0 < 49) {
                __half2 hh;
                hh.x = __float2half_rn(oAcc[nt][0]);
                hh.y = __float2half_rn(oAcc[nt][1]);
                *(__half2*)(g_ah + ((size_t)(b * 49 + r0)) * 256 + h * 32 + d) = hh;
            }
            if (r1 < 49) {
                __half2 hh;
                hh.x = __float2half_rn(oAcc[nt][2]);
                hh.y = __float2half_rn(oAcc[nt][3]);
                *(__half2*)(g_ah + ((size_t)(b * 49 + r1)) * 256 + h * 32 + d) = hh;
            }
        }
    }
}

extern "C" void kernel_launch(void* const* d_in, const int* in_sizes, int n_in,
                              void* d_out, int out_size) {
    const float* x      = (const float*)d_in[0];
    const float* mask   = (const float*)d_in[1];
    const float* fg     = (const float*)d_in[2];
    const float* bg     = (const float*)d_in[3];
    const float* qkv_w  = (const float*)d_in[4];
    const float* qkv_b  = (const float*)d_in[5];
    const float* proj_w = (const float*)d_in[6];
    const float* proj_b = (const float*)d_in[7];
    const float* table  = (const float*)d_in[8];
    float* out = (float*)d_out;

    cudaFuncSetAttribute(hgemm<0>, cudaFuncAttributeMaxDynamicSharedMemorySize, GEMM_SMEM);
    cudaFuncSetAttribute(hgemm<1>, cudaFuncAttributeMaxDynamicSharedMemorySize, GEMM_SMEM);

    __half* xh;    cudaGetSymbolAddress((void**)&xh,    g_xh);
    __half* wqkv;  cudaGetSymbolAddress((void**)&wqkv,  g_wqkv);
    __half* wproj; cudaGetSymbolAddress((void**)&wproj, g_wproj);
    __half* ah;    cudaGetSymbolAddress((void**)&ah,    g_ah);

    // Launch order puts attn_kernel in the ncu capture slot (#3).
    conv_all<<<(CONV_ROWS * 64 + 255) / 256, 256>>>(x, qkv_w, proj_w);   // 0
    hgemm<0><<<dim3(6, 784), 256, GEMM_SMEM>>>(xh, wqkv, qkv_b, nullptr);// 1
    emb_kernel<<<(64 * NHEAD * NN + 255) / 256, 256>>>(table, mask);     // 2
    attn_kernel<<<B_TOT * NHEAD, 128>>>(fg, bg);                         // 3
    hgemm<1><<<dim3(2, 784), 256, GEMM_SMEM>>>(ah, wproj, proj_b, out);  // 4
}

// round 17
// speedup vs baseline: 1.3622x; 1.0216x over previous
#include <cuda_runtime.h>
#include <cuda_fp16.h>
#include <cstdint>
#include <cstddef>

typedef unsigned long long u64;
typedef unsigned int u32;

#define B_TOT 2048
#define N_TOK 49
#define CDIM  256
#define NHEAD 8
#define HDIM  32
#define M_ROWS (B_TOT * N_TOK)      // 100352
#define NN 2401                      // 49*49
#define CONV_ROWS (M_ROWS + 768 + 256)

// -------- scratch (device globals: no allocation allowed) --------
__device__ __align__(16) __half g_qh[(size_t)B_TOT * NHEAD * N_TOK * HDIM];
__device__ __align__(16) __half g_kh[(size_t)B_TOT * NHEAD * N_TOK * HDIM];
__device__ __align__(16) __half g_vh[(size_t)B_TOT * NHEAD * N_TOK * HDIM];
__device__ __align__(16) __half g_xh[(size_t)M_ROWS * 256];    // x fp16
__device__ __align__(16) __half g_ah[(size_t)M_ROWS * 256];    // attn-out fp16
__device__ __align__(16) __half g_wqkv[768 * 256];             // fp16
__device__ __align__(16) __half g_wproj[256 * 256];            // fp16
__device__ float g_emb[64 * NHEAD * NN];   // exp(mask[w] + rel_pos_bias[h])

// -------- smem / async-copy / mma helpers (standard PTX, sm_80-safe) --------
__device__ __forceinline__ u32 smem_u32(const void* p) {
    u32 a; asm("{ .reg .u64 t; cvta.to.shared.u64 t,%1; cvt.u32.u64 %0,t; }" : "=r"(a) : "l"(p));
    return a;
}
__device__ __forceinline__ void cp16(u32 dst, const void* src) {
    asm volatile("cp.async.cg.shared.global [%0], [%1], 16;" :: "r"(dst), "l"(src));
}
__device__ __forceinline__ void ldm4(u32* r, u32 addr) {
    asm volatile("ldmatrix.sync.aligned.m8n8.x4.shared.b16 {%0,%1,%2,%3},[%4];"
                 : "=r"(r[0]), "=r"(r[1]), "=r"(r[2]), "=r"(r[3]) : "r"(addr));
}
__device__ __forceinline__ void ldm4t(u32* r, u32 addr) {
    asm volatile("ldmatrix.sync.aligned.m8n8.x4.trans.shared.b16 {%0,%1,%2,%3},[%4];"
                 : "=r"(r[0]), "=r"(r[1]), "=r"(r[2]), "=r"(r[3]) : "r"(addr));
}
__device__ __forceinline__ void hmma16816(float* c, const u32* a, const u32* b) {
    asm volatile(
        "mma.sync.aligned.m16n8k16.row.col.f32.f16.f16.f32 "
        "{%0,%1,%2,%3},{%4,%5,%6,%7},{%8,%9},{%0,%1,%2,%3};"
        : "+f"(c[0]), "+f"(c[1]), "+f"(c[2]), "+f"(c[3])
        : "r"(a[0]), "r"(a[1]), "r"(a[2]), "r"(a[3]), "r"(b[0]), "r"(b[1]));
}

// -------- merged fp32 -> fp16 conversion: x | qkv_w | proj_w --------
__global__ void conv_all(const float* __restrict__ x,
                         const float* __restrict__ qkv_w,
                         const float* __restrict__ proj_w) {
    int t = blockIdx.x * blockDim.x + threadIdx.x;
    if (t >= CONV_ROWS * 64) return;
    int m = t >> 6, k4 = (t & 63) << 2;
    const float* src;
    __half* dst;
    int row;
    if (m < M_ROWS)            { src = x;      dst = g_xh;    row = m; }
    else if (m < M_ROWS + 768) { src = qkv_w;  dst = g_wqkv;  row = m - M_ROWS; }
    else                       { src = proj_w; dst = g_wproj; row = m - M_ROWS - 768; }
    float4 v = *(const float4*)(src + (size_t)row * 256 + k4);
    __half2 a;
    __half* dh = dst + (size_t)row * 256 + k4;
    a.x = __float2half_rn(v.x); a.y = __float2half_rn(v.y); *(__half2*)(dh) = a;
    a.x = __float2half_rn(v.z); a.y = __float2half_rn(v.w); *(__half2*)(dh + 2) = a;
}

// -------- precompute exp(mask[w][i][j] + bias[h][i][j]) --------
__global__ void emb_kernel(const float* __restrict__ table,
                           const float* __restrict__ mask) {
    int t = blockIdx.x * blockDim.x + threadIdx.x;
    if (t >= 64 * NHEAD * NN) return;
    int w   = t / (NHEAD * NN);
    int rem = t - w * (NHEAD * NN);
    int h   = rem / NN;
    int ij  = rem - h * NN;
    int i = ij / 49, j = ij - i * 49;
    int ri = i / 7, ci = i - ri * 7;
    int rj = j / 7, cj = j - rj * 7;
    int idx = (ri - rj + 6) * 13 + (ci - cj + 6);
    g_emb[t] = __expf(mask[w * NN + ij] + table[idx * NHEAD + h]);
}

// -------- HMMA GEMM (1-term fp16): C = A[M,256] @ W[N,256]^T + bias --------
// __launch_bounds__(256,2): R12-verified occupancy fix.
// MODE 0: writes fp16 q/k/v. MODE 1: writes fp32 d_out.
#define TSTRIDE 112
#define TILE_B  (128 * TSTRIDE)
#define STAGE_B (2 * TILE_B)
#define GEMM_SMEM (2 * STAGE_B)

template<int MODE>
__global__ void __launch_bounds__(256, 2) hgemm(const __half* __restrict__ Ah_,
                                                const __half* __restrict__ Wh_,
                                                const float* __restrict__ bias,
                                                float* __restrict__ out) {
    extern __shared__ char smem[];
    const u32 sb = smem_u32(smem);
    const int tid = threadIdx.x;
    const int wid = tid >> 5, lane = tid & 31;
    const int g = lane >> 2, t = lane & 3;
    const int wm = wid >> 2, wn = wid & 3;
    const int bn = blockIdx.x, bm = blockIdx.y;

    const char* Asrc = (const char*)(Ah_ + (size_t)(bm * 128) * 256);
    const char* Wsrc = (const char*)(Wh_ + (size_t)(bn * 128) * 256);

    float acc[4][4][4];
#pragma unroll
    for (int i = 0; i < 4; i++)
#pragma unroll
        for (int j = 0; j < 4; j++)
#pragma unroll
            for (int q = 0; q < 4; q++) acc[i][j][q] = 0.f;

    const int r_ld = tid >> 2, c4 = tid & 3;

    auto issue = [&](int s) {
        const u32 dbase = sb + (s & 1) * STAGE_B;
#pragma unroll
        for (int i = 0; i < 2; i++) {
            const int r = r_ld + i * 64;
            const u32 d = dbase + r * TSTRIDE + c4 * 16;
            const size_t go = (size_t)r * 512 + (size_t)s * 64 + c4 * 16;
            cp16(d + 0 * TILE_B, Asrc + go);
            cp16(d + 1 * TILE_B, Wsrc + go);
        }
        asm volatile("cp.async.commit_group;" ::: "memory");
    };

    const u32 a_lrow = (lane & 15);
    const u32 a_lcol = (lane >> 4) << 4;
    const u32 b_lrow = ((lane >> 4) << 3) + (lane & 7);
    const u32 b_lcol = ((lane >> 3) & 1) << 4;

    issue(0);
    for (int s = 0; s < 8; s++) {
        if (s < 7) {
            issue(s + 1);
            asm volatile("cp.async.wait_group 1;" ::: "memory");
        } else {
            asm volatile("cp.async.wait_group 0;" ::: "memory");
        }
        __syncthreads();

        const u32 stb = sb + (s & 1) * STAGE_B;
        const u32 A0 = stb, B0 = stb + TILE_B;
#pragma unroll
        for (int s2 = 0; s2 < 2; s2++) {
            const u32 kbase = s2 * 32;
            u32 ah[4][4], bh[4][2];
#pragma unroll
            for (int mt = 0; mt < 4; mt++) {
                const u32 ra = (wm * 64 + mt * 16 + a_lrow) * TSTRIDE + kbase + a_lcol;
                ldm4(ah[mt], A0 + ra);
            }
#pragma unroll
            for (int nt2 = 0; nt2 < 2; nt2++) {
                u32 btmp[4];
                const u32 rb = (wn * 32 + nt2 * 16 + b_lrow) * TSTRIDE + kbase + b_lcol;
                ldm4(btmp, B0 + rb);
                bh[nt2 * 2 + 0][0] = btmp[0]; bh[nt2 * 2 + 0][1] = btmp[1];
                bh[nt2 * 2 + 1][0] = btmp[2]; bh[nt2 * 2 + 1][1] = btmp[3];
            }
#pragma unroll
            for (int mt = 0; mt < 4; mt++)
#pragma unroll
                for (int nt = 0; nt < 4; nt++)
                    hmma16816(acc[mt][nt], ah[mt], bh[nt]);
        }
        __syncthreads();
    }

#pragma unroll
    for (int nt = 0; nt < 4; nt++) {
        const int col0 = bn * 128 + wn * 32 + nt * 8 + t * 2;
        const float b0 = bias[col0], b1 = bias[col0 + 1];
        if (MODE == 0) {
            const int part = col0 >> 8;
            const int h = (col0 >> 5) & 7;
            const int d0 = col0 & 31;
            const float scale = (part == 0) ? 0.17677669529663687f : 1.0f;
            __half* dstb = (part == 0) ? g_qh : ((part == 1) ? g_kh : g_vh);
#pragma unroll
            for (int mt = 0; mt < 4; mt++) {
                const float* c = acc[mt][nt];
#pragma unroll
                for (int rr = 0; rr < 2; rr++) {
                    const int m = bm * 128 + wm * 64 + mt * 16 + g + rr * 8;
                    const int bidx = m / 49, tok = m - bidx * 49;
                    __half* dst = dstb + ((size_t)(bidx * 8 + h) * 49 + tok) * 32 + d0;
                    __half2 v;
                    v.x = __float2half_rn((c[rr * 2 + 0] + b0) * scale);
                    v.y = __float2half_rn((c[rr * 2 + 1] + b1) * scale);
                    *(__half2*)dst = v;
                }
            }
        } else {
#pragma unroll
            for (int mt = 0; mt < 4; mt++) {
                const float* c = acc[mt][nt];
#pragma unroll
                for (int rr = 0; rr < 2; rr++) {
                    const int m = bm * 128 + wm * 64 + mt * 16 + g + rr * 8;
                    float2 v;
                    v.x = c[rr * 2 + 0] + b0;
                    v.y = c[rr * 2 + 1] + b1;
                    *(float2*)(out + (size_t)m * 256 + col0) = v;
                }
            }
        }
    }
}

// -------- HMMA fused attention: one block per (batch, head), 4 warps --------
// V stored row-major; PV B-fragments via ldmatrix.trans (no scalar transpose).
// Smem aliased: sPh reuses sQh/sKh space after the S phase. 8 blocks/SM.
#define QKS 80    // sQh/sKh row stride BYTES
#define VS  80    // sV row stride BYTES (row-major [j][d], 32 halfs + pad)
#define PS  144   // sPh row stride BYTES
#define OFF_Q  0
#define OFF_K  5120
#define OFF_P  0          // aliased over Q + part of K (needs 9216 <= 10240)
#define OFF_V  10240      // 64 rows x 80B = 5120
#define OFF_E  15360      // 49*53 fp32 = 10388
#define SM_BYTES 25760

__global__ void __launch_bounds__(128, 8) attn_kernel(const float* __restrict__ fg,
                                                      const float* __restrict__ bg) {
    __shared__ __align__(16) char sm[SM_BYTES];
    __half* sQh = (__half*)(sm + OFF_Q);
    __half* sKh = (__half*)(sm + OFF_K);
    __half* sPh = (__half*)(sm + OFF_P);   // alias of Q/K region
    __half* sV  = (__half*)(sm + OFF_V);   // row-major [j][40]
    float*  sE  = (float*)(sm + OFF_E);

    const int bh = blockIdx.x;
    const int b = bh >> 3, h = bh & 7;
    const int tid = threadIdx.x;
    const int warp = tid >> 5, lane = tid & 31;
    const int g = lane >> 2, t = lane & 3;

    const u32 sQa = smem_u32(sQh), sKa = smem_u32(sKh);
    const u32 sVa = smem_u32(sV),  sPa = smem_u32(sPh);

    // zero V pad rows 49..63 (75 uint4) — disjoint from the load region below,
    // so no barrier is needed between this and the loads.
    {
        const uint4 z = make_uint4(0u, 0u, 0u, 0u);
        for (int i = tid; i < 75; i += 128)
            ((uint4*)((char*)sV + 49 * VS))[i] = z;
    }

    // load q/k/v (all row-major fp16, vectorized)
    const size_t base = (size_t)bh * (N_TOK * HDIM);
    for (int f = tid; f < 196; f += 128) {
        const int j = f >> 2, c = f & 3;     // row j, 16B chunk c
        uint4 qv = ((const uint4*)(g_qh + base))[f];
        *(uint4*)((char*)sQh + j * QKS + c * 16) = qv;
        uint4 kv = ((const uint4*)(g_kh + base))[f];
        *(uint4*)((char*)sKh + j * QKS + c * 16) = kv;
        uint4 vv = ((const uint4*)(g_vh + base))[f];
        *(uint4*)((char*)sV + j * VS + c * 16) = vv;
    }
    // q/k rows 49..63 are garbage — S rows/cols >=49 are discarded by guards.
    __syncthreads();

    // ldmatrix per-lane offsets
    const u32 a_lrow = (lane & 15);
    const u32 a_lcol = (lane >> 4) << 4;
    const u32 b_lrow = ((lane >> 4) << 3) + (lane & 7);
    const u32 b_lcol = ((lane >> 3) & 1) << 4;
    // trans-V per-lane offsets: row = k-dim, bytecol = n-dim
    const u32 vb_lrow = ((lane >> 3) & 1) * 8 + (lane & 7);
    const u32 vb_lcol = (lane >> 4) << 4;

    // ---- S = Q K^T: warp handles rows warp*16..+15, all 64 cols ----
    {
        float sAcc[8][4];
#pragma unroll
        for (int i = 0; i < 8; i++)
#pragma unroll
            for (int q = 0; q < 4; q++) sAcc[i][q] = 0.f;

#pragma unroll
        for (int ks = 0; ks < 2; ks++) {
            u32 a[4];
            ldm4(a, sQa + (warp * 16 + a_lrow) * QKS + ks * 32 + a_lcol);
#pragma unroll
            for (int nt2 = 0; nt2 < 4; nt2++) {
                u32 btmp[4];
                ldm4(btmp, sKa + (nt2 * 16 + b_lrow) * QKS + ks * 32 + b_lcol);
                hmma16816(sAcc[nt2 * 2 + 0], a, btmp + 0);
                hmma16816(sAcc[nt2 * 2 + 1], a, btmp + 2);
            }
        }

        // epilogue: E0 = exp(S) * emb -> sE (fp32), guarded
        const float* embh = g_emb + (size_t)((b & 63) * NHEAD + h) * NN;
        const int r0 = warp * 16 + g;
        const int r1 = r0 + 8;
#pragma unroll
        for (int nt = 0; nt < 8; nt++) {
            const int col = nt * 8 + t * 2;
            if (col < 49) {
                const bool c1ok = (col + 1 < 49);
                if (r0 < 49) {
                    sE[r0 * 53 + col] = __expf(sAcc[nt][0]) * embh[r0 * 49 + col];
                    if (c1ok) sE[r0 * 53 + col + 1] = __expf(sAcc[nt][1]) * embh[r0 * 49 + col + 1];
                }
                if (r1 < 49) {
                    sE[r1 * 53 + col] = __expf(sAcc[nt][2]) * embh[r1 * 49 + col];
                    if (c1ok) sE[r1 * 53 + col + 1] = __expf(sAcc[nt][3]) * embh[r1 * 49 + col + 1];
                }
            }
        }
    }
    __syncthreads();        // S-phase reads of sQh/sKh complete

    // zero the aliased sPh (576 uint4) — pads must be 0 for PV HMMA
    {
        const uint4 z = make_uint4(0u, 0u, 0u, 0u);
        for (int i = tid; i < 576; i += 128) ((uint4*)sPh)[i] = z;
    }
    __syncthreads();

    // ---- one-pass triple softmax (warp per row); P -> fp16 sPh ----
    for (int row = warp; row < 49; row += 4) {
        const float* er = sE + row * 53;
        const float* fgr = fg + (size_t)b * NN + row * 49;
        const float* bgr = bg + (size_t)b * NN + row * 49;
        bool ok = lane < 17;
        float e0  = er[lane];
        float fga = __expf(fgr[lane]), bga = __expf(bgr[lane]);
        float e0b = 0.f, fgb = 0.f, bgb = 0.f;
        if (ok) {
            e0b = er[lane + 32];
            fgb = __expf(fgr[lane + 32]);
            bgb = __expf(bgr[lane + 32]);
        }
        float s0 = e0 + e0b;
        float sf = e0 * fga + e0b * fgb;
        float sb2 = e0 * bga + e0b * bgb;
#pragma unroll
        for (int o = 16; o; o >>= 1) {
            s0  += __shfl_xor_sync(0xffffffffu, s0, o);
            sf  += __shfl_xor_sync(0xffffffffu, sf, o);
            sb2 += __shfl_xor_sync(0xffffffffu, sb2, o);
        }
        float r0f = 1.f / s0, rff = 1.f / sf, rbf = 1.f / sb2;
        sPh[row * 72 + lane] = __float2half_rn(e0 * (r0f + rff * fga - rbf * bga));
        if (ok) sPh[row * 72 + lane + 32] = __float2half_rn(e0b * (r0f + rff * fgb - rbf * bgb));
    }
    __syncthreads();

    // ---- O = P @ V: m=16/warp, n=32, k=64; V fragments via ldmatrix.trans ----
    {
        float oAcc[4][4];
#pragma unroll
        for (int i = 0; i < 4; i++)
#pragma unroll
            for (int q = 0; q < 4; q++) oAcc[i][q] = 0.f;

#pragma unroll
        for (int ks = 0; ks < 4; ks++) {
            u32 a[4];
            ldm4(a, sPa + (warp * 16 + a_lrow) * PS + ks * 32 + a_lcol);
#pragma unroll
            for (int nt2 = 0; nt2 < 2; nt2++) {
                u32 btmp[4];
                ldm4t(btmp, sVa + (ks * 16 + vb_lrow) * VS + nt2 * 32 + vb_lcol);
                hmma16816(oAcc[nt2 * 2 + 0], a, btmp + 0);
                hmma16816(oAcc[nt2 * 2 + 1], a, btmp + 2);
            }
        }

        const int r0 = warp * 16 + g;
        const int r1 = r0 + 8;
#pragma unroll
        for (int nt = 0; nt < 4; nt++) {
            const int d = nt * 8 + t * 2;
            if (r0 < 49) {
                __half2 hh;
                hh.x = __float2half_rn(oAcc[nt][0]);
                hh.y = __float2half_rn(oAcc[nt][1]);
                *(__half2*)(g_ah + ((size_t)(b * 49 + r0)) * 256 + h * 32 + d) = hh;
            }
            if (r1 < 49) {
                __half2 hh;
                hh.x = __float2half_rn(oAcc[nt][2]);
                hh.y = __float2half_rn(oAcc[nt][3]);
                *(__half2*)(g_ah + ((size_t)(b * 49 + r1)) * 256 + h * 32 + d) = hh;
            }
        }
    }
}

extern "C" void kernel_launch(void* const* d_in, const int* in_sizes, int n_in,
                              void* d_out, int out_size) {
    const float* x      = (const float*)d_in[0];
    const float* mask   = (const float*)d_in[1];
    const float* fg     = (const float*)d_in[2];
    const float* bg     = (const float*)d_in[3];
    const float* qkv_w  = (const float*)d_in[4];
    const float* qkv_b  = (const float*)d_in[5];
    const float* proj_w = (const float*)d_in[6];
    const float* proj_b = (const float*)d_in[7];
    const float* table  = (const float*)d_in[8];
    float* out = (float*)d_out;

    cudaFuncSetAttribute(hgemm<0>, cudaFuncAttributeMaxDynamicSharedMemorySize, GEMM_SMEM);
    cudaFuncSetAttribute(hgemm<1>, cudaFuncAttributeMaxDynamicSharedMemorySize, GEMM_SMEM);

    __half* xh;    cudaGetSymbolAddress((void**)&xh,    g_xh);
    __half* wqkv;  cudaGetSymbolAddress((void**)&wqkv,  g_wqkv);
    __half* wproj; cudaGetSymbolAddress((void**)&wproj, g_wproj);
    __half* ah;    cudaGetSymbolAddress((void**)&ah,    g_ah);

    // Launch order puts attn_kernel in the ncu capture slot (#3).
    conv_all<<<(CONV_ROWS * 64 + 255) / 256, 256>>>(x, qkv_w, proj_w);   // 0
    hgemm<0><<<dim3(6, 784), 256, GEMM_SMEM>>>(xh, wqkv, qkv_b, nullptr);// 1
    emb_kernel<<<(64 * NHEAD * NN + 255) / 256, 256>>>(table, mask);     // 2
    attn_kernel<<<B_TOT * NHEAD, 128>>>(fg, bg);                         // 3
    hgemm<1><<<dim3(2, 784), 256, GEMM_SMEM>>>(ah, wproj, proj_b, out);  // 4
}